// round 5
// baseline (speedup 1.0000x reference)
#include <cuda_runtime.h>
#include <cstdint>

#define NN 50000
#define EE 640000
#define GGR 256
#define HH 128

// ---------------- scratch (device globals; no allocs allowed) ----------------
__device__ __align__(16) float g_h[NN * HH];
__device__ __align__(16) float g_z[NN * HH];
__device__ __align__(16) float g_tb[NN * HH];          // temp (also [N,64] gate hidden)
__device__ __align__(16) float g_e[(size_t)EE * HH];   // edge features, 327MB
__device__ int g_deg[NN];
__device__ int g_off[NN];
__device__ int g_cur[NN];
__device__ int g_eperm[EE];
__device__ int g_sperm[EE];
__device__ float g_gate[NN];
__device__ float g_wexp[NN];
__device__ unsigned g_gmaxk[GGR];
__device__ float g_den[GGR];
__device__ __align__(16) float g_pool[GGR * HH];
__device__ __align__(16) float g_ht[GGR * HH];

// ---------------- CSR build ----------------
__global__ void hist_kernel(const int* __restrict__ ei, int* __restrict__ deg, int E) {
    int e = blockIdx.x * blockDim.x + threadIdx.x;
    if (e < E) atomicAdd(&deg[ei[E + e]], 1);
}

__global__ __launch_bounds__(1024) void scan_kernel(const int* __restrict__ deg,
                                                    int* __restrict__ off, int n) {
    __shared__ int s[1024];
    __shared__ int carry;
    int tid = threadIdx.x;
    if (tid == 0) carry = 0;
    __syncthreads();
    for (int base = 0; base < n; base += 1024) {
        int v = (base + tid < n) ? deg[base + tid] : 0;
        s[tid] = v;
        __syncthreads();
        for (int d = 1; d < 1024; d <<= 1) {
            int t = (tid >= d) ? s[tid - d] : 0;
            __syncthreads();
            if (tid >= d) s[tid] += t;
            __syncthreads();
        }
        if (base + tid < n) off[base + tid] = carry + s[tid] - v;  // exclusive
        __syncthreads();
        if (tid == 0) carry += s[1023];
        __syncthreads();
    }
}

__global__ void scatter_kernel(const int* __restrict__ ei, const int* __restrict__ off,
                               int* __restrict__ cur, int* __restrict__ eperm,
                               int* __restrict__ sperm, int E) {
    int e = blockIdx.x * blockDim.x + threadIdx.x;
    if (e >= E) return;
    int d = ei[E + e];
    int pos = off[d] + atomicAdd(&cur[d], 1);
    eperm[pos] = e;
    sperm[pos] = ei[e];
}

// ---------------- generic tiled GEMM: C[M,NC] = op(A[M,K] @ W[K,NC] + b) ----------------
// tile 64 rows x NC cols, 256 threads, micro-tile 4 rows x (NC/16) cols
template <int K, int NC, bool RELU, bool BN>
__global__ __launch_bounds__(256) void gemm_kernel(
    const float* __restrict__ A, const float* __restrict__ W, const float* __restrict__ bias,
    const float* __restrict__ gamma, const float* __restrict__ beta,
    float* __restrict__ C, int M) {
    extern __shared__ float smem[];
    float* Ws = smem;                 // K*NC
    float* As = smem + K * NC;        // 64*(K+1)
    const int LDA = K + 1;
    const int tid = threadIdx.x;
    const int row0 = blockIdx.x * 64;

    for (int i = tid; i < K * NC; i += 256) Ws[i] = W[i];
    for (int i = tid; i < 64 * K; i += 256) {
        int r = i / K, c = i - r * K;
        int gr = row0 + r;
        As[r * LDA + c] = (gr < M) ? A[(size_t)gr * K + c] : 0.f;
    }
    __syncthreads();

    constexpr int CPT = NC / 16;
    const int cg = tid & 15, rg = tid >> 4;
    const int c0 = cg * CPT, r0 = rg * 4;

    float acc[4][CPT];
#pragma unroll
    for (int i = 0; i < 4; i++)
#pragma unroll
        for (int j = 0; j < CPT; j++) acc[i][j] = 0.f;

#pragma unroll 8
    for (int k = 0; k < K; k++) {
        float a0 = As[(r0 + 0) * LDA + k];
        float a1 = As[(r0 + 1) * LDA + k];
        float a2 = As[(r0 + 2) * LDA + k];
        float a3 = As[(r0 + 3) * LDA + k];
#pragma unroll
        for (int j = 0; j < CPT; j++) {
            float w = Ws[k * NC + c0 + j];
            acc[0][j] += a0 * w;
            acc[1][j] += a1 * w;
            acc[2][j] += a2 * w;
            acc[3][j] += a3 * w;
        }
    }

    const float bnsc = 0.99999500003749968f;  // 1/sqrt(1+1e-5)
#pragma unroll
    for (int i = 0; i < 4; i++) {
        int gr = row0 + r0 + i;
        if (gr < M) {
#pragma unroll
            for (int j = 0; j < CPT; j++) {
                float v = acc[i][j] + bias[c0 + j];
                if (BN) v = v * (bnsc * gamma[c0 + j]) + beta[c0 + j];
                if (RELU) v = fmaxf(v, 0.f);
                C[(size_t)gr * NC + c0 + j] = v;
            }
        }
    }
}

// ---------------- fused edge encoder: e = relu(ea@W1+b1)@W2+b2 ----------------
__global__ __launch_bounds__(256) void edge_encoder_kernel(
    const float* __restrict__ EA, const float* __restrict__ W1, const float* __restrict__ b1,
    const float* __restrict__ W2, const float* __restrict__ b2,
    float* __restrict__ Eout, int Ecnt) {
    extern __shared__ float smem[];
    float* W1s = smem;            // 16*128 = 2048
    float* W2s = W1s + 2048;      // 128*128 = 16384
    float* EAs = W2s + 16384;     // 64*16 = 1024
    float* Hs = EAs + 1024;       // 64*129 = 8256
    const int tid = threadIdx.x;
    const int e0 = blockIdx.x * 64;

    for (int i = tid; i < 2048; i += 256) W1s[i] = W1[i];
    for (int i = tid; i < 16384; i += 256) W2s[i] = W2[i];
    for (int i = tid; i < 1024; i += 256) {
        int r = i >> 4, c = i & 15;
        int ge = e0 + r;
        EAs[i] = (ge < Ecnt) ? EA[(size_t)ge * 16 + c] : 0.f;
    }
    __syncthreads();

    // phase 1: hidden = relu(ea @ W1 + b1), 64x128 outputs, 2 threads/col
    {
        int col = tid & 127, half = tid >> 7;
        float bb = b1[col];
        for (int r = half; r < 64; r += 2) {
            float s = bb;
#pragma unroll
            for (int k = 0; k < 16; k++) s += EAs[r * 16 + k] * W1s[k * 128 + col];
            Hs[r * 129 + col] = fmaxf(s, 0.f);
        }
    }
    __syncthreads();

    // phase 2: out = hidden @ W2 + b2
    const int cg = tid & 15, rg = tid >> 4;
    const int c0 = cg * 8, r0 = rg * 4;
    float acc[4][8];
#pragma unroll
    for (int i = 0; i < 4; i++)
#pragma unroll
        for (int j = 0; j < 8; j++) acc[i][j] = 0.f;

#pragma unroll 8
    for (int k = 0; k < 128; k++) {
        float a0 = Hs[(r0 + 0) * 129 + k];
        float a1 = Hs[(r0 + 1) * 129 + k];
        float a2 = Hs[(r0 + 2) * 129 + k];
        float a3 = Hs[(r0 + 3) * 129 + k];
#pragma unroll
        for (int j = 0; j < 8; j++) {
            float w = W2s[k * 128 + c0 + j];
            acc[0][j] += a0 * w;
            acc[1][j] += a1 * w;
            acc[2][j] += a2 * w;
            acc[3][j] += a3 * w;
        }
    }
#pragma unroll
    for (int i = 0; i < 4; i++) {
        int ge = e0 + r0 + i;
        if (ge < Ecnt) {
#pragma unroll
            for (int j = 0; j < 8; j++)
                Eout[(size_t)ge * 128 + c0 + j] = acc[i][j] + b2[c0 + j];
        }
    }
}

// ---------------- per-layer message + aggregate: z = h + sum relu(h[src]+e) ----------------
__global__ __launch_bounds__(256) void aggregate_kernel(
    const float* __restrict__ h, const float* __restrict__ e,
    const int* __restrict__ off, const int* __restrict__ deg,
    const int* __restrict__ eperm, const int* __restrict__ sperm,
    float* __restrict__ z, int n) {
    int w = (blockIdx.x * blockDim.x + threadIdx.x) >> 5;
    int lane = threadIdx.x & 31;
    if (w >= n) return;
    const float4* h4 = reinterpret_cast<const float4*>(h);
    const float4* e4 = reinterpret_cast<const float4*>(e);
    float4 acc = h4[w * 32 + lane];
    int s0 = off[w], d = deg[w];
    for (int j = s0; j < s0 + d; j++) {
        int ei = eperm[j];
        int si = sperm[j];
        float4 ev = __ldcs(&e4[(size_t)ei * 32 + lane]);  // streaming: don't evict h from L2
        float4 hv = h4[si * 32 + lane];
        acc.x += fmaxf(ev.x + hv.x, 0.f);
        acc.y += fmaxf(ev.y + hv.y, 0.f);
        acc.z += fmaxf(ev.z + hv.z, 0.f);
        acc.w += fmaxf(ev.w + hv.w, 0.f);
    }
    reinterpret_cast<float4*>(z)[w * 32 + lane] = acc;
}

// ---------------- pooling ----------------
__global__ void gate2_kernel(const float* __restrict__ hid, const float* __restrict__ w2,
                             const float* __restrict__ b2, float* __restrict__ gate, int n) {
    int w = (blockIdx.x * blockDim.x + threadIdx.x) >> 5;
    int lane = threadIdx.x & 31;
    if (w >= n) return;
    float s = hid[w * 64 + lane] * w2[lane] + hid[w * 64 + 32 + lane] * w2[32 + lane];
#pragma unroll
    for (int o = 16; o > 0; o >>= 1) s += __shfl_down_sync(0xffffffffu, s, o);
    if (lane == 0) gate[w] = s + b2[0];
}

__device__ __forceinline__ unsigned f2ord(float f) {
    unsigned b = __float_as_uint(f);
    return (b & 0x80000000u) ? ~b : (b | 0x80000000u);
}
__device__ __forceinline__ float ord2f(unsigned k) {
    return __uint_as_float((k & 0x80000000u) ? (k & 0x7fffffffu) : ~k);
}

__global__ void smax_kernel(const float* __restrict__ gate, const int* __restrict__ batch,
                            unsigned* __restrict__ gmaxk, int n) {
    int i = blockIdx.x * blockDim.x + threadIdx.x;
    if (i < n) atomicMax(&gmaxk[batch[i]], f2ord(gate[i]));
}

__global__ void wexp_kernel(const float* __restrict__ gate, const int* __restrict__ batch,
                            const unsigned* __restrict__ gmaxk, float* __restrict__ wexp,
                            float* __restrict__ den, int n) {
    int i = blockIdx.x * blockDim.x + threadIdx.x;
    if (i >= n) return;
    float m = ord2f(gmaxk[batch[i]]);
    float w = expf(gate[i] - m);
    wexp[i] = w;
    atomicAdd(&den[batch[i]], w);
}

__global__ void pool_kernel(const float* __restrict__ h, const int* __restrict__ batch,
                            const float* __restrict__ wexp, const float* __restrict__ den,
                            float* __restrict__ pool, int n) {
    int w = (blockIdx.x * blockDim.x + threadIdx.x) >> 5;
    int lane = threadIdx.x & 31;
    if (w >= n) return;
    int b = batch[w];
    float alpha = wexp[w] / den[b];
#pragma unroll
    for (int j = 0; j < 4; j++) {
        int c = lane + 32 * j;
        atomicAdd(&pool[b * HH + c], alpha * h[(size_t)w * HH + c]);
    }
}

__global__ void head2_kernel(const float* __restrict__ ht, const float* __restrict__ w2,
                             const float* __restrict__ b2, float* __restrict__ out,
                             int G, int T) {
    int i = blockIdx.x * blockDim.x + threadIdx.x;
    if (i >= G * T) return;
    int g = i / T, t = i - g * T;
    float s = b2[t];
    for (int k = 0; k < HH; k++) s += ht[g * HH + k] * w2[k * T + t];
    out[i] = s;
}

// ---------------- launch ----------------
extern "C" void kernel_launch(void* const* d_in, const int* in_sizes, int n_in,
                              void* d_out, int out_size) {
    const float* x = (const float*)d_in[0];
    const float* edge_attr = (const float*)d_in[1];
    const float* node_w = (const float*)d_in[2];
    const float* node_b = (const float*)d_in[3];
    const float* edge_w1 = (const float*)d_in[4];
    const float* edge_b1 = (const float*)d_in[5];
    const float* edge_w2 = (const float*)d_in[6];
    const float* edge_b2 = (const float*)d_in[7];
    const float* conv_w1 = (const float*)d_in[8];
    const float* conv_b1 = (const float*)d_in[9];
    const float* conv_w2 = (const float*)d_in[10];
    const float* conv_b2 = (const float*)d_in[11];
    const float* bn_gamma = (const float*)d_in[12];
    const float* bn_beta = (const float*)d_in[13];
    const float* gate_w1 = (const float*)d_in[14];
    const float* gate_b1 = (const float*)d_in[15];
    const float* gate_w2 = (const float*)d_in[16];
    const float* gate_b2 = (const float*)d_in[17];
    const float* head_w1 = (const float*)d_in[18];
    const float* head_b1 = (const float*)d_in[19];
    const float* head_w2 = (const float*)d_in[20];
    const float* head_b2 = (const float*)d_in[21];
    const int* edge_index = (const int*)d_in[22];
    const int* batch = (const int*)d_in[23];

    const int N = in_sizes[0] / 64;
    const int E = in_sizes[22] / 2;
    const int T = 5;
    const int G = out_size / T;

    float *h, *z, *tb, *e, *gate, *wexp, *den, *pool, *ht;
    int *deg, *off, *cur, *eperm, *sperm;
    unsigned* gmaxk;
    cudaGetSymbolAddress((void**)&h, g_h);
    cudaGetSymbolAddress((void**)&z, g_z);
    cudaGetSymbolAddress((void**)&tb, g_tb);
    cudaGetSymbolAddress((void**)&e, g_e);
    cudaGetSymbolAddress((void**)&deg, g_deg);
    cudaGetSymbolAddress((void**)&off, g_off);
    cudaGetSymbolAddress((void**)&cur, g_cur);
    cudaGetSymbolAddress((void**)&eperm, g_eperm);
    cudaGetSymbolAddress((void**)&sperm, g_sperm);
    cudaGetSymbolAddress((void**)&gate, g_gate);
    cudaGetSymbolAddress((void**)&wexp, g_wexp);
    cudaGetSymbolAddress((void**)&gmaxk, g_gmaxk);
    cudaGetSymbolAddress((void**)&den, g_den);
    cudaGetSymbolAddress((void**)&pool, g_pool);
    cudaGetSymbolAddress((void**)&ht, g_ht);

    // dynamic smem opt-in (immediate API, not stream-ordered; safe under capture)
    const int SM_G64 = (64 * 128 + 64 * 65) * 4;      // 49408
    const int SM_G128 = (128 * 128 + 64 * 129) * 4;   // 98560
    const int SM_G128_64 = (128 * 64 + 64 * 129) * 4; // 65792
    const int SM_EDGE = (2048 + 16384 + 1024 + 64 * 129) * 4;  // 110848
    cudaFuncSetAttribute(gemm_kernel<64, 128, false, false>, cudaFuncAttributeMaxDynamicSharedMemorySize, SM_G64);
    cudaFuncSetAttribute(gemm_kernel<128, 128, true, false>, cudaFuncAttributeMaxDynamicSharedMemorySize, SM_G128);
    cudaFuncSetAttribute(gemm_kernel<128, 128, true, true>, cudaFuncAttributeMaxDynamicSharedMemorySize, SM_G128);
    cudaFuncSetAttribute(gemm_kernel<128, 64, true, false>, cudaFuncAttributeMaxDynamicSharedMemorySize, SM_G128_64);
    cudaFuncSetAttribute(edge_encoder_kernel, cudaFuncAttributeMaxDynamicSharedMemorySize, SM_EDGE);

    // zero scratch
    cudaMemsetAsync(deg, 0, (size_t)N * 4, 0);
    cudaMemsetAsync(cur, 0, (size_t)N * 4, 0);
    cudaMemsetAsync(gmaxk, 0, (size_t)G * 4, 0);
    cudaMemsetAsync(den, 0, (size_t)G * 4, 0);
    cudaMemsetAsync(pool, 0, (size_t)G * HH * 4, 0);

    // CSR by dst
    hist_kernel<<<(E + 255) / 256, 256>>>(edge_index, deg, E);
    scan_kernel<<<1, 1024>>>(deg, off, N);
    scatter_kernel<<<(E + 255) / 256, 256>>>(edge_index, off, cur, eperm, sperm, E);

    // encoders
    gemm_kernel<64, 128, false, false><<<(N + 63) / 64, 256, SM_G64>>>(
        x, node_w, node_b, nullptr, nullptr, h, N);
    edge_encoder_kernel<<<(E + 63) / 64, 256, SM_EDGE>>>(
        edge_attr, edge_w1, edge_b1, edge_w2, edge_b2, e, E);

    // 4 GINE layers
    for (int l = 0; l < 4; l++) {
        aggregate_kernel<<<(N + 7) / 8, 256>>>(h, e, off, deg, eperm, sperm, z, N);
        gemm_kernel<128, 128, true, false><<<(N + 63) / 64, 256, SM_G128>>>(
            z, conv_w1 + (size_t)l * HH * HH, conv_b1 + l * HH, nullptr, nullptr, tb, N);
        gemm_kernel<128, 128, true, true><<<(N + 63) / 64, 256, SM_G128>>>(
            tb, conv_w2 + (size_t)l * HH * HH, conv_b2 + l * HH,
            bn_gamma + l * HH, bn_beta + l * HH, h, N);
    }

    // gate MLP + segment softmax pooling
    gemm_kernel<128, 64, true, false><<<(N + 63) / 64, 256, SM_G128_64>>>(
        h, gate_w1, gate_b1, nullptr, nullptr, tb, N);
    gate2_kernel<<<(N + 7) / 8, 256>>>(tb, gate_w2, gate_b2, gate, N);
    smax_kernel<<<(N + 255) / 256, 256>>>(gate, batch, gmaxk, N);
    wexp_kernel<<<(N + 255) / 256, 256>>>(gate, batch, gmaxk, wexp, den, N);
    pool_kernel<<<(N + 7) / 8, 256>>>(h, batch, wexp, den, pool, N);

    // head
    gemm_kernel<128, 128, true, false><<<(G + 63) / 64, 256, SM_G128>>>(
        pool, head_w1, head_b1, nullptr, nullptr, ht, G);
    head2_kernel<<<(G * T + 255) / 256, 256>>>(ht, head_w2, head_b2, (float*)d_out, G, T);
}

// round 7
// speedup vs baseline: 2.0993x; 2.0993x over previous
#include <cuda_runtime.h>
#include <cuda_bf16.h>
#include <cstdint>

#define NN 50000
#define EE 640000
#define GGR 256
#define HH 128

// ---------------- scratch (device globals; no allocs allowed) ----------------
__device__ __align__(16) float g_h[NN * HH];
__device__ __align__(16) float g_z[NN * HH];
__device__ __align__(16) float g_tb[NN * HH];
__device__ __align__(16) float g_e[(size_t)EE * HH];
__device__ int g_deg[NN];
__device__ int g_off[NN];
__device__ int g_cur[NN];
__device__ int g_eperm[EE];
__device__ int g_sperm[EE];
__device__ float g_gate[NN];
__device__ float g_wexp[NN];
__device__ unsigned g_gmaxk[GGR];
__device__ float g_den[GGR];
__device__ __align__(16) float g_pool[GGR * HH];
__device__ __align__(16) float g_ht[GGR * HH];

// split-bf16 weights, [K][N] row-major with padded pitch PB=N+8, hi/lo
__device__ __align__(16) __nv_bfloat16 g_wnh[64 * 136],  g_wnl[64 * 136];     // node_w
__device__ __align__(16) __nv_bfloat16 g_c1h[4 * 128 * 136], g_c1l[4 * 128 * 136];
__device__ __align__(16) __nv_bfloat16 g_c2h[4 * 128 * 136], g_c2l[4 * 128 * 136];
__device__ __align__(16) __nv_bfloat16 g_wgh[128 * 72],  g_wgl[128 * 72];     // gate_w1 N=64
__device__ __align__(16) __nv_bfloat16 g_whh[128 * 136], g_whl[128 * 136];    // head_w1
__device__ __align__(16) __nv_bfloat16 g_e1h[16 * 136],  g_e1l[16 * 136];     // edge_w1
__device__ __align__(16) __nv_bfloat16 g_e2h[128 * 136], g_e2l[128 * 136];    // edge_w2

// ---------------- helpers ----------------
__device__ __forceinline__ uint32_t smem_u32(const void* p) {
    uint32_t a;
    asm("{ .reg .u64 t; cvta.to.shared.u64 t, %1; cvt.u32.u64 %0, t; }" : "=r"(a) : "l"(p));
    return a;
}
__device__ __forceinline__ uint32_t bfpair(__nv_bfloat16 a, __nv_bfloat16 b) {
    __nv_bfloat162 v = __halves2bfloat162(a, b);
    return *reinterpret_cast<uint32_t*>(&v);
}
__device__ __forceinline__ void split1(float x, __nv_bfloat16& h, __nv_bfloat16& l) {
    h = __float2bfloat16(x);
    l = __float2bfloat16(x - __bfloat162float(h));
}

__device__ __forceinline__ void ldsm_x4(uint32_t* r, uint32_t addr) {
    asm volatile("ldmatrix.sync.aligned.m8n8.x4.shared.b16 {%0,%1,%2,%3}, [%4];"
                 : "=r"(r[0]), "=r"(r[1]), "=r"(r[2]), "=r"(r[3]) : "r"(addr));
}
__device__ __forceinline__ void ldsm_x4t(uint32_t* r, uint32_t addr) {
    asm volatile("ldmatrix.sync.aligned.m8n8.x4.trans.shared.b16 {%0,%1,%2,%3}, [%4];"
                 : "=r"(r[0]), "=r"(r[1]), "=r"(r[2]), "=r"(r[3]) : "r"(addr));
}
__device__ __forceinline__ void mma16816(float* d, const uint32_t* a, const uint32_t* b) {
    asm volatile(
        "mma.sync.aligned.m16n8k16.row.col.f32.bf16.bf16.f32 "
        "{%0,%1,%2,%3}, {%4,%5,%6,%7}, {%8,%9}, {%0,%1,%2,%3};"
        : "+f"(d[0]), "+f"(d[1]), "+f"(d[2]), "+f"(d[3])
        : "r"(a[0]), "r"(a[1]), "r"(a[2]), "r"(a[3]), "r"(b[0]), "r"(b[1]));
}

// ---------------- weight split+pad into scratch: W[K,N] fp32 -> [K][PB] bf16 hi/lo ----
__global__ void wconv_kernel(const float* __restrict__ W, int K, int N, int PB,
                             __nv_bfloat16* __restrict__ hi, __nv_bfloat16* __restrict__ lo) {
    int i = blockIdx.x * blockDim.x + threadIdx.x;
    if (i >= K * PB) return;
    int k = i / PB, n = i - k * PB;
    float x = (n < N) ? W[(size_t)k * N + n] : 0.f;
    __nv_bfloat16 h, l;
    split1(x, h, l);
    hi[i] = h;
    lo[i] = l;
}

// ---------------- tensor-core (mma.sync) GEMM: C = op(A[M,K] @ W[K,NC] + b) ----------
template <int K, int NC, bool RELU, bool BN>
__global__ void __launch_bounds__(256) mma_gemm(
    const float* __restrict__ A, const __nv_bfloat16* __restrict__ Bhi,
    const __nv_bfloat16* __restrict__ Blo, const float* __restrict__ bias,
    const float* __restrict__ gamma, const float* __restrict__ beta,
    float* __restrict__ C, int M) {
    constexpr int PA = K + 8;
    constexpr int PB = NC + 8;
    constexpr int NF = NC / 16;  // n-frags per warp (warp covers NC/2 cols)
    extern __shared__ __align__(16) char smc[];
    __nv_bfloat16* Ah = (__nv_bfloat16*)smc;
    __nv_bfloat16* Al = Ah + 128 * PA;
    __nv_bfloat16* Bh = Al + 128 * PA;
    __nv_bfloat16* Bl = Bh + K * PB;

    const int tid = threadIdx.x;
    const int lane = tid & 31, w = tid >> 5;
    const int wm = (w & 3) * 32;
    const int wn = (w >> 2) * (NC / 2);
    const int m0 = blockIdx.x * 128;

    // B copy (pre-split/padded in global scratch)
    {
        const float4* sh = (const float4*)Bhi;
        const float4* sl = (const float4*)Blo;
        float4* dh = (float4*)Bh;
        float4* dl = (float4*)Bl;
        for (int i = tid; i < K * PB / 8; i += 256) { dh[i] = sh[i]; dl[i] = sl[i]; }
    }
    // A: fp32 -> split bf16 hi/lo; 2 threads per row
    {
        int r = tid >> 1, half = tid & 1;
        int gr = m0 + r;
        bool v = gr < M;
        const float4* a4 = (const float4*)(A + (size_t)gr * K) + half * (K / 8);
        __nv_bfloat16* th = Ah + r * PA + half * (K / 2);
        __nv_bfloat16* tl = Al + r * PA + half * (K / 2);
#pragma unroll
        for (int i = 0; i < K / 8; i++) {
            float4 x = v ? a4[i] : make_float4(0.f, 0.f, 0.f, 0.f);
            __nv_bfloat16 h0, h1, h2, h3, l0, l1, l2, l3;
            split1(x.x, h0, l0); split1(x.y, h1, l1);
            split1(x.z, h2, l2); split1(x.w, h3, l3);
            *(uint32_t*)(th + i * 4) = bfpair(h0, h1);
            *(uint32_t*)(th + i * 4 + 2) = bfpair(h2, h3);
            *(uint32_t*)(tl + i * 4) = bfpair(l0, l1);
            *(uint32_t*)(tl + i * 4 + 2) = bfpair(l2, l3);
        }
    }
    __syncthreads();

    float acc[2][NF][4];
#pragma unroll
    for (int i = 0; i < 2; i++)
#pragma unroll
        for (int j = 0; j < NF; j++)
#pragma unroll
            for (int q = 0; q < 4; q++) acc[i][j][q] = 0.f;

    const uint32_t Ahb = smem_u32(Ah), Alb = smem_u32(Al);
    const uint32_t Bhb = smem_u32(Bh), Blb = smem_u32(Bl);
    const int a_row = lane & 15, a_kof = (lane >> 4) << 3;
    const int b_mat = lane >> 3, b_r = lane & 7;
    const int b_krow = ((b_mat & 1) << 3) + b_r;
    const int b_ncol = (b_mat >> 1) << 3;

#pragma unroll
    for (int ks = 0; ks < K / 16; ks++) {
        const int k0 = ks * 16;
        uint32_t ahf[2][4], alf[2][4];
#pragma unroll
        for (int mi = 0; mi < 2; mi++) {
            uint32_t off = ((wm + mi * 16 + a_row) * PA + k0 + a_kof) * 2;
            ldsm_x4(ahf[mi], Ahb + off);
            ldsm_x4(alf[mi], Alb + off);
        }
#pragma unroll
        for (int np = 0; np < NF / 2; np++) {
            uint32_t off = ((k0 + b_krow) * PB + wn + np * 16 + b_ncol) * 2;
            uint32_t bhf[4], blf[4];
            ldsm_x4t(bhf, Bhb + off);
            ldsm_x4t(blf, Blb + off);
#pragma unroll
            for (int mi = 0; mi < 2; mi++) {
                mma16816(acc[mi][2 * np], ahf[mi], bhf);
                mma16816(acc[mi][2 * np], ahf[mi], blf);
                mma16816(acc[mi][2 * np], alf[mi], bhf);
                mma16816(acc[mi][2 * np + 1], ahf[mi], bhf + 2);
                mma16816(acc[mi][2 * np + 1], ahf[mi], blf + 2);
                mma16816(acc[mi][2 * np + 1], alf[mi], bhf + 2);
            }
        }
    }

    const float bnsc = 0.99999500003749968f;  // 1/sqrt(1+1e-5)
    const int rbase = m0 + wm + (lane >> 2);
    const int cbase = wn + (lane & 3) * 2;
#pragma unroll
    for (int mi = 0; mi < 2; mi++) {
#pragma unroll
        for (int nj = 0; nj < NF; nj++) {
            int col = cbase + nj * 8;
            float b0 = bias[col], b1v = bias[col + 1];
#pragma unroll
            for (int hh = 0; hh < 2; hh++) {
                int row = rbase + mi * 16 + hh * 8;
                if (row < M) {
                    float v0 = acc[mi][nj][hh * 2 + 0] + b0;
                    float v1 = acc[mi][nj][hh * 2 + 1] + b1v;
                    if (BN) {
                        v0 = v0 * (bnsc * gamma[col]) + beta[col];
                        v1 = v1 * (bnsc * gamma[col + 1]) + beta[col + 1];
                    }
                    if (RELU) { v0 = fmaxf(v0, 0.f); v1 = fmaxf(v1, 0.f); }
                    float2 o = make_float2(v0, v1);
                    *(float2*)(C + (size_t)row * NC + col) = o;
                }
            }
        }
    }
}

// ---------------- fused edge encoder: e = relu(ea@W1+b1)@W2+b2, 128 edges/block ------
__global__ void __launch_bounds__(256) edge_mma_kernel(
    const float* __restrict__ EA,
    const __nv_bfloat16* __restrict__ W1h, const __nv_bfloat16* __restrict__ W1l,
    const __nv_bfloat16* __restrict__ W2h, const __nv_bfloat16* __restrict__ W2l,
    const float* __restrict__ b1, const float* __restrict__ b2,
    float* __restrict__ Eout, int E) {
    constexpr int PA1 = 24;   // K=16 + 8
    constexpr int PW = 136;   // N=128 + 8 (also pitch of A2, K=128+8)
    extern __shared__ __align__(16) char smc[];
    __nv_bfloat16* A1h = (__nv_bfloat16*)smc;          // 128*24
    __nv_bfloat16* A1l = A1h + 128 * PA1;
    __nv_bfloat16* Q1h = A1l + 128 * PA1;              // W1: 16*136
    __nv_bfloat16* Q1l = Q1h + 16 * PW;
    __nv_bfloat16* A2h = Q1l + 16 * PW;                // 128*136
    __nv_bfloat16* A2l = A2h + 128 * PW;
    __nv_bfloat16* Q2h = A2l + 128 * PW;               // W2: 128*136
    __nv_bfloat16* Q2l = Q2h + 128 * PW;

    const int tid = threadIdx.x;
    const int lane = tid & 31, w = tid >> 5;
    const int wm = (w & 3) * 32;
    const int wn = (w >> 2) * 64;
    const int m0 = blockIdx.x * 128;

    // weights copy
    {
        const float4* s1h = (const float4*)W1h; const float4* s1l = (const float4*)W1l;
        const float4* s2h = (const float4*)W2h; const float4* s2l = (const float4*)W2l;
        float4* d1h = (float4*)Q1h; float4* d1l = (float4*)Q1l;
        float4* d2h = (float4*)Q2h; float4* d2l = (float4*)Q2l;
        for (int i = tid; i < 16 * PW / 8; i += 256) { d1h[i] = s1h[i]; d1l[i] = s1l[i]; }
        for (int i = tid; i < 128 * PW / 8; i += 256) { d2h[i] = s2h[i]; d2l[i] = s2l[i]; }
    }
    // A1 fill: 2 threads/row, 8 elems each
    {
        int r = tid >> 1, half = tid & 1;
        int ge = m0 + r;
        bool v = ge < E;
        const float4* a4 = (const float4*)(EA + (size_t)ge * 16) + half * 2;
        __nv_bfloat16* th = A1h + r * PA1 + half * 8;
        __nv_bfloat16* tl = A1l + r * PA1 + half * 8;
#pragma unroll
        for (int i = 0; i < 2; i++) {
            float4 x = v ? a4[i] : make_float4(0.f, 0.f, 0.f, 0.f);
            __nv_bfloat16 h0, h1, h2, h3, l0, l1, l2, l3;
            split1(x.x, h0, l0); split1(x.y, h1, l1);
            split1(x.z, h2, l2); split1(x.w, h3, l3);
            *(uint32_t*)(th + i * 4) = bfpair(h0, h1);
            *(uint32_t*)(th + i * 4 + 2) = bfpair(h2, h3);
            *(uint32_t*)(tl + i * 4) = bfpair(l0, l1);
            *(uint32_t*)(tl + i * 4 + 2) = bfpair(l2, l3);
        }
    }
    __syncthreads();

    const int a_row = lane & 15, a_kof = (lane >> 4) << 3;
    const int b_mat = lane >> 3, b_r = lane & 7;
    const int b_krow = ((b_mat & 1) << 3) + b_r;
    const int b_ncol = (b_mat >> 1) << 3;
    const int frow = lane >> 2, fcol = (lane & 3) * 2;

    float acc[2][8][4];
#pragma unroll
    for (int i = 0; i < 2; i++)
#pragma unroll
        for (int j = 0; j < 8; j++)
#pragma unroll
            for (int q = 0; q < 4; q++) acc[i][j][q] = 0.f;

    // ---- phase 1: hidden = ea @ W1 (single k16 step) ----
    {
        const uint32_t A1hb = smem_u32(A1h), A1lb = smem_u32(A1l);
        const uint32_t Q1hb = smem_u32(Q1h), Q1lb = smem_u32(Q1l);
        uint32_t ahf[2][4], alf[2][4];
#pragma unroll
        for (int mi = 0; mi < 2; mi++) {
            uint32_t off = ((wm + mi * 16 + a_row) * PA1 + a_kof) * 2;
            ldsm_x4(ahf[mi], A1hb + off);
            ldsm_x4(alf[mi], A1lb + off);
        }
#pragma unroll
        for (int np = 0; np < 4; np++) {
            uint32_t off = (b_krow * PW + wn + np * 16 + b_ncol) * 2;
            uint32_t bhf[4], blf[4];
            ldsm_x4t(bhf, Q1hb + off);
            ldsm_x4t(blf, Q1lb + off);
#pragma unroll
            for (int mi = 0; mi < 2; mi++) {
                mma16816(acc[mi][2 * np], ahf[mi], bhf);
                mma16816(acc[mi][2 * np], ahf[mi], blf);
                mma16816(acc[mi][2 * np], alf[mi], bhf);
                mma16816(acc[mi][2 * np + 1], ahf[mi], bhf + 2);
                mma16816(acc[mi][2 * np + 1], ahf[mi], blf + 2);
                mma16816(acc[mi][2 * np + 1], alf[mi], bhf + 2);
            }
        }
    }
    // relu + bias, re-split into A2 smem directly from fragments
#pragma unroll
    for (int mi = 0; mi < 2; mi++) {
#pragma unroll
        for (int nj = 0; nj < 8; nj++) {
            int col = wn + nj * 8 + fcol;
            float c0 = b1[col], c1 = b1[col + 1];
#pragma unroll
            for (int hh = 0; hh < 2; hh++) {
                int row = wm + mi * 16 + hh * 8 + frow;
                float v0 = fmaxf(acc[mi][nj][hh * 2 + 0] + c0, 0.f);
                float v1 = fmaxf(acc[mi][nj][hh * 2 + 1] + c1, 0.f);
                __nv_bfloat16 h0, h1, l0, l1;
                split1(v0, h0, l0); split1(v1, h1, l1);
                *(uint32_t*)(A2h + row * PW + col) = bfpair(h0, h1);
                *(uint32_t*)(A2l + row * PW + col) = bfpair(l0, l1);
            }
        }
    }
    __syncthreads();

    // ---- phase 2: e = hidden @ W2, K=128 ----
#pragma unroll
    for (int i = 0; i < 2; i++)
#pragma unroll
        for (int j = 0; j < 8; j++)
#pragma unroll
            for (int q = 0; q < 4; q++) acc[i][j][q] = 0.f;
    {
        const uint32_t A2hb = smem_u32(A2h), A2lb = smem_u32(A2l);
        const uint32_t Q2hb = smem_u32(Q2h), Q2lb = smem_u32(Q2l);
#pragma unroll
        for (int ks = 0; ks < 8; ks++) {
            const int k0 = ks * 16;
            uint32_t ahf[2][4], alf[2][4];
#pragma unroll
            for (int mi = 0; mi < 2; mi++) {
                uint32_t off = ((wm + mi * 16 + a_row) * PW + k0 + a_kof) * 2;
                ldsm_x4(ahf[mi], A2hb + off);
                ldsm_x4(alf[mi], A2lb + off);
            }
#pragma unroll
            for (int np = 0; np < 4; np++) {
                uint32_t off = ((k0 + b_krow) * PW + wn + np * 16 + b_ncol) * 2;
                uint32_t bhf[4], blf[4];
                ldsm_x4t(bhf, Q2hb + off);
                ldsm_x4t(blf, Q2lb + off);
#pragma unroll
                for (int mi = 0; mi < 2; mi++) {
                    mma16816(acc[mi][2 * np], ahf[mi], bhf);
                    mma16816(acc[mi][2 * np], ahf[mi], blf);
                    mma16816(acc[mi][2 * np], alf[mi], bhf);
                    mma16816(acc[mi][2 * np + 1], ahf[mi], bhf + 2);
                    mma16816(acc[mi][2 * np + 1], ahf[mi], blf + 2);
                    mma16816(acc[mi][2 * np + 1], alf[mi], bhf + 2);
                }
            }
        }
    }
    // epilogue: e = acc + b2
#pragma unroll
    for (int mi = 0; mi < 2; mi++) {
#pragma unroll
        for (int nj = 0; nj < 8; nj++) {
            int col = wn + nj * 8 + fcol;
            float c0 = b2[col], c1 = b2[col + 1];
#pragma unroll
            for (int hh = 0; hh < 2; hh++) {
                int row = m0 + wm + mi * 16 + hh * 8 + frow;
                if (row < E) {
                    float2 o = make_float2(acc[mi][nj][hh * 2 + 0] + c0,
                                           acc[mi][nj][hh * 2 + 1] + c1);
                    *(float2*)(Eout + (size_t)row * 128 + col) = o;
                }
            }
        }
    }
}

// ---------------- CSR build ----------------
__global__ void hist_kernel(const int* __restrict__ ei, int* __restrict__ deg, int E) {
    int e = blockIdx.x * blockDim.x + threadIdx.x;
    if (e < E) atomicAdd(&deg[ei[E + e]], 1);
}

__global__ __launch_bounds__(1024) void scan_kernel(const int* __restrict__ deg,
                                                    int* __restrict__ off, int n) {
    __shared__ int s[1024];
    __shared__ int carry;
    int tid = threadIdx.x;
    if (tid == 0) carry = 0;
    __syncthreads();
    for (int base = 0; base < n; base += 1024) {
        int v = (base + tid < n) ? deg[base + tid] : 0;
        s[tid] = v;
        __syncthreads();
        for (int d = 1; d < 1024; d <<= 1) {
            int t = (tid >= d) ? s[tid - d] : 0;
            __syncthreads();
            if (tid >= d) s[tid] += t;
            __syncthreads();
        }
        if (base + tid < n) off[base + tid] = carry + s[tid] - v;
        __syncthreads();
        if (tid == 0) carry += s[1023];
        __syncthreads();
    }
}

__global__ void scatter_kernel(const int* __restrict__ ei, const int* __restrict__ off,
                               int* __restrict__ cur, int* __restrict__ eperm,
                               int* __restrict__ sperm, int E) {
    int e = blockIdx.x * blockDim.x + threadIdx.x;
    if (e >= E) return;
    int d = ei[E + e];
    int pos = off[d] + atomicAdd(&cur[d], 1);
    eperm[pos] = e;
    sperm[pos] = ei[e];
}

// ---------------- message + aggregate: z = h + sum relu(h[src]+e) ----------------
__global__ __launch_bounds__(256) void aggregate_kernel(
    const float* __restrict__ h, const float* __restrict__ e,
    const int* __restrict__ off, const int* __restrict__ deg,
    const int* __restrict__ eperm, const int* __restrict__ sperm,
    float* __restrict__ z, int n) {
    int w = (blockIdx.x * blockDim.x + threadIdx.x) >> 5;
    int lane = threadIdx.x & 31;
    if (w >= n) return;
    const float4* h4 = reinterpret_cast<const float4*>(h);
    const float4* e4 = reinterpret_cast<const float4*>(e);
    float4 acc = h4[w * 32 + lane];
    int s0 = off[w], d = deg[w];
    for (int j = s0; j < s0 + d; j++) {
        int ei = eperm[j];
        int si = sperm[j];
        float4 ev = __ldcs(&e4[(size_t)ei * 32 + lane]);
        float4 hv = h4[si * 32 + lane];
        acc.x += fmaxf(ev.x + hv.x, 0.f);
        acc.y += fmaxf(ev.y + hv.y, 0.f);
        acc.z += fmaxf(ev.z + hv.z, 0.f);
        acc.w += fmaxf(ev.w + hv.w, 0.f);
    }
    reinterpret_cast<float4*>(z)[w * 32 + lane] = acc;
}

// ---------------- pooling ----------------
__global__ void gate2_kernel(const float* __restrict__ hid, const float* __restrict__ w2,
                             const float* __restrict__ b2, float* __restrict__ gate, int n) {
    int w = (blockIdx.x * blockDim.x + threadIdx.x) >> 5;
    int lane = threadIdx.x & 31;
    if (w >= n) return;
    float s = hid[w * 64 + lane] * w2[lane] + hid[w * 64 + 32 + lane] * w2[32 + lane];
#pragma unroll
    for (int o = 16; o > 0; o >>= 1) s += __shfl_down_sync(0xffffffffu, s, o);
    if (lane == 0) gate[w] = s + b2[0];
}

__device__ __forceinline__ unsigned f2ord(float f) {
    unsigned b = __float_as_uint(f);
    return (b & 0x80000000u) ? ~b : (b | 0x80000000u);
}
__device__ __forceinline__ float ord2f(unsigned k) {
    return __uint_as_float((k & 0x80000000u) ? (k & 0x7fffffffu) : ~k);
}

__global__ void smax_kernel(const float* __restrict__ gate, const int* __restrict__ batch,
                            unsigned* __restrict__ gmaxk, int n) {
    int i = blockIdx.x * blockDim.x + threadIdx.x;
    if (i < n) atomicMax(&gmaxk[batch[i]], f2ord(gate[i]));
}

__global__ void wexp_kernel(const float* __restrict__ gate, const int* __restrict__ batch,
                            const unsigned* __restrict__ gmaxk, float* __restrict__ wexp,
                            float* __restrict__ den, int n) {
    int i = blockIdx.x * blockDim.x + threadIdx.x;
    if (i >= n) return;
    float m = ord2f(gmaxk[batch[i]]);
    float w = expf(gate[i] - m);
    wexp[i] = w;
    atomicAdd(&den[batch[i]], w);
}

__global__ void pool_kernel(const float* __restrict__ h, const int* __restrict__ batch,
                            const float* __restrict__ wexp, const float* __restrict__ den,
                            float* __restrict__ pool, int n) {
    int w = (blockIdx.x * blockDim.x + threadIdx.x) >> 5;
    int lane = threadIdx.x & 31;
    if (w >= n) return;
    int b = batch[w];
    float alpha = wexp[w] / den[b];
#pragma unroll
    for (int j = 0; j < 4; j++) {
        int c = lane + 32 * j;
        atomicAdd(&pool[b * HH + c], alpha * h[(size_t)w * HH + c]);
    }
}

__global__ void head2_kernel(const float* __restrict__ ht, const float* __restrict__ w2,
                             const float* __restrict__ b2, float* __restrict__ out,
                             int G, int T) {
    int i = blockIdx.x * blockDim.x + threadIdx.x;
    if (i >= G * T) return;
    int g = i / T, t = i - g * T;
    float s = b2[t];
    for (int k = 0; k < HH; k++) s += ht[g * HH + k] * w2[k * T + t];
    out[i] = s;
}

// ---------------- launch ----------------
extern "C" void kernel_launch(void* const* d_in, const int* in_sizes, int n_in,
                              void* d_out, int out_size) {
    const float* x = (const float*)d_in[0];
    const float* edge_attr = (const float*)d_in[1];
    const float* node_w = (const float*)d_in[2];
    const float* node_b = (const float*)d_in[3];
    const float* edge_w1 = (const float*)d_in[4];
    const float* edge_b1 = (const float*)d_in[5];
    const float* edge_w2 = (const float*)d_in[6];
    const float* edge_b2 = (const float*)d_in[7];
    const float* conv_w1 = (const float*)d_in[8];
    const float* conv_b1 = (const float*)d_in[9];
    const float* conv_w2 = (const float*)d_in[10];
    const float* conv_b2 = (const float*)d_in[11];
    const float* bn_gamma = (const float*)d_in[12];
    const float* bn_beta = (const float*)d_in[13];
    const float* gate_w1 = (const float*)d_in[14];
    const float* gate_b1 = (const float*)d_in[15];
    const float* gate_w2 = (const float*)d_in[16];
    const float* gate_b2 = (const float*)d_in[17];
    const float* head_w1 = (const float*)d_in[18];
    const float* head_b1 = (const float*)d_in[19];
    const float* head_w2 = (const float*)d_in[20];
    const float* head_b2 = (const float*)d_in[21];
    const int* edge_index = (const int*)d_in[22];
    const int* batch = (const int*)d_in[23];

    const int N = in_sizes[0] / 64;
    const int E = in_sizes[22] / 2;
    const int T = 5;
    const int G = out_size / T;

    float *h, *z, *tb, *e, *gate, *wexp, *den, *pool, *ht;
    int *deg, *off, *cur, *eperm, *sperm;
    unsigned* gmaxk;
    cudaGetSymbolAddress((void**)&h, g_h);
    cudaGetSymbolAddress((void**)&z, g_z);
    cudaGetSymbolAddress((void**)&tb, g_tb);
    cudaGetSymbolAddress((void**)&e, g_e);
    cudaGetSymbolAddress((void**)&deg, g_deg);
    cudaGetSymbolAddress((void**)&off, g_off);
    cudaGetSymbolAddress((void**)&cur, g_cur);
    cudaGetSymbolAddress((void**)&eperm, g_eperm);
    cudaGetSymbolAddress((void**)&sperm, g_sperm);
    cudaGetSymbolAddress((void**)&gate, g_gate);
    cudaGetSymbolAddress((void**)&wexp, g_wexp);
    cudaGetSymbolAddress((void**)&gmaxk, g_gmaxk);
    cudaGetSymbolAddress((void**)&den, g_den);
    cudaGetSymbolAddress((void**)&pool, g_pool);
    cudaGetSymbolAddress((void**)&ht, g_ht);

    __nv_bfloat16 *wnh, *wnl, *c1h, *c1l, *c2h, *c2l, *wgh, *wgl, *whh, *whl,
        *e1h, *e1l, *e2h, *e2l;
    cudaGetSymbolAddress((void**)&wnh, g_wnh); cudaGetSymbolAddress((void**)&wnl, g_wnl);
    cudaGetSymbolAddress((void**)&c1h, g_c1h); cudaGetSymbolAddress((void**)&c1l, g_c1l);
    cudaGetSymbolAddress((void**)&c2h, g_c2h); cudaGetSymbolAddress((void**)&c2l, g_c2l);
    cudaGetSymbolAddress((void**)&wgh, g_wgh); cudaGetSymbolAddress((void**)&wgl, g_wgl);
    cudaGetSymbolAddress((void**)&whh, g_whh); cudaGetSymbolAddress((void**)&whl, g_whl);
    cudaGetSymbolAddress((void**)&e1h, g_e1h); cudaGetSymbolAddress((void**)&e1l, g_e1l);
    cudaGetSymbolAddress((void**)&e2h, g_e2h); cudaGetSymbolAddress((void**)&e2l, g_e2l);

    // dynamic smem sizes (bytes)
    const int SM_N1 = (2 * 128 * 72 + 2 * 64 * 136) * 2;     // K=64,NC=128 -> 71680
    const int SM_N2 = (2 * 128 * 136 + 2 * 128 * 136) * 2;   // K=128,NC=128 -> 139264
    const int SM_G = (2 * 128 * 136 + 2 * 128 * 72) * 2;     // K=128,NC=64 -> 106496
    const int SM_EDGE = (2 * 128 * 24 + 2 * 16 * 136 + 4 * 128 * 136) * 2;  // 160256
    cudaFuncSetAttribute(mma_gemm<64, 128, false, false>, cudaFuncAttributeMaxDynamicSharedMemorySize, SM_N1);
    cudaFuncSetAttribute(mma_gemm<128, 128, true, false>, cudaFuncAttributeMaxDynamicSharedMemorySize, SM_N2);
    cudaFuncSetAttribute(mma_gemm<128, 128, true, true>, cudaFuncAttributeMaxDynamicSharedMemorySize, SM_N2);
    cudaFuncSetAttribute(mma_gemm<128, 64, true, false>, cudaFuncAttributeMaxDynamicSharedMemorySize, SM_G);
    cudaFuncSetAttribute(edge_mma_kernel, cudaFuncAttributeMaxDynamicSharedMemorySize, SM_EDGE);

    // zero scratch
    cudaMemsetAsync(deg, 0, (size_t)N * 4, 0);
    cudaMemsetAsync(cur, 0, (size_t)N * 4, 0);
    cudaMemsetAsync(gmaxk, 0, (size_t)G * 4, 0);
    cudaMemsetAsync(den, 0, (size_t)G * 4, 0);
    cudaMemsetAsync(pool, 0, (size_t)G * HH * 4, 0);

    // weight prep (split + pad)
    wconv_kernel<<<(64 * 136 + 255) / 256, 256>>>(node_w, 64, 128, 136, wnh, wnl);
    for (int l = 0; l < 4; l++) {
        wconv_kernel<<<(128 * 136 + 255) / 256, 256>>>(
            conv_w1 + (size_t)l * 16384, 128, 128, 136,
            c1h + (size_t)l * 128 * 136, c1l + (size_t)l * 128 * 136);
        wconv_kernel<<<(128 * 136 + 255) / 256, 256>>>(
            conv_w2 + (size_t)l * 16384, 128, 128, 136,
            c2h + (size_t)l * 128 * 136, c2l + (size_t)l * 128 * 136);
    }
    wconv_kernel<<<(128 * 72 + 255) / 256, 256>>>(gate_w1, 128, 64, 72, wgh, wgl);
    wconv_kernel<<<(128 * 136 + 255) / 256, 256>>>(head_w1, 128, 128, 136, whh, whl);
    wconv_kernel<<<(16 * 136 + 255) / 256, 256>>>(edge_w1, 16, 128, 136, e1h, e1l);
    wconv_kernel<<<(128 * 136 + 255) / 256, 256>>>(edge_w2, 128, 128, 136, e2h, e2l);

    // CSR by dst
    hist_kernel<<<(E + 255) / 256, 256>>>(edge_index, deg, E);
    scan_kernel<<<1, 1024>>>(deg, off, N);
    scatter_kernel<<<(E + 255) / 256, 256>>>(edge_index, off, cur, eperm, sperm, E);

    // encoders (tensor pipe via mma.sync)
    mma_gemm<64, 128, false, false><<<(N + 127) / 128, 256, SM_N1>>>(
        x, wnh, wnl, node_b, nullptr, nullptr, h, N);
    edge_mma_kernel<<<(E + 127) / 128, 256, SM_EDGE>>>(
        edge_attr, e1h, e1l, e2h, e2l, edge_b1, edge_b2, e, E);

    // 4 GINE layers
    for (int l = 0; l < 4; l++) {
        aggregate_kernel<<<(N + 7) / 8, 256>>>(h, e, off, deg, eperm, sperm, z, N);
        mma_gemm<128, 128, true, false><<<(N + 127) / 128, 256, SM_N2>>>(
            z, c1h + (size_t)l * 128 * 136, c1l + (size_t)l * 128 * 136, conv_b1 + l * HH,
            nullptr, nullptr, tb, N);
        mma_gemm<128, 128, true, true><<<(N + 127) / 128, 256, SM_N2>>>(
            tb, c2h + (size_t)l * 128 * 136, c2l + (size_t)l * 128 * 136, conv_b2 + l * HH,
            bn_gamma + l * HH, bn_beta + l * HH, h, N);
    }

    // gate MLP + segment softmax pooling
    mma_gemm<128, 64, true, false><<<(N + 127) / 128, 256, SM_G>>>(
        h, wgh, wgl, gate_b1, nullptr, nullptr, tb, N);
    gate2_kernel<<<(N + 7) / 8, 256>>>(tb, gate_w2, gate_b2, gate, N);
    smax_kernel<<<(N + 255) / 256, 256>>>(gate, batch, gmaxk, N);
    wexp_kernel<<<(N + 255) / 256, 256>>>(gate, batch, gmaxk, wexp, den, N);
    pool_kernel<<<(N + 7) / 8, 256>>>(h, batch, wexp, den, pool, N);

    // head
    mma_gemm<128, 128, true, false><<<(G + 127) / 128, 256, SM_N2>>>(
        pool, whh, whl, head_b1, nullptr, nullptr, ht, G);
    head2_kernel<<<(G * T + 255) / 256, 256>>>(ht, head_w2, head_b2, (float*)d_out, G, T);
}

// round 8
// speedup vs baseline: 2.4018x; 1.1441x over previous
#include <cuda_runtime.h>
#include <cuda_bf16.h>
#include <cstdint>

#define NN 50000
#define EE 640000
#define GGR 256
#define HH 128

// ---------------- scratch (device globals; no allocs allowed) ----------------
__device__ __align__(16) float g_h[NN * HH];
__device__ __align__(16) float g_z[NN * HH];
__device__ __align__(16) float g_tb[NN * HH];
__device__ __align__(16) float g_e[(size_t)EE * HH];   // used as bf16[E*128]
__device__ int g_deg[NN];
__device__ int g_off[NN];
__device__ int g_cur[NN];
__device__ int g_eperm[EE];
__device__ int g_sperm[EE];
__device__ float g_gate[NN];
__device__ float g_wexp[NN];
__device__ unsigned g_gmaxk[GGR];
__device__ float g_den[GGR];
__device__ __align__(16) float g_pool[GGR * HH];
__device__ __align__(16) float g_ht[GGR * HH];

// split-bf16 weights, [K][N] row-major with padded pitch PB=N+8, hi/lo
__device__ __align__(16) __nv_bfloat16 g_wnh[64 * 136],  g_wnl[64 * 136];     // node_w
__device__ __align__(16) __nv_bfloat16 g_c1h[4 * 128 * 136], g_c1l[4 * 128 * 136];
__device__ __align__(16) __nv_bfloat16 g_c2h[4 * 128 * 136], g_c2l[4 * 128 * 136];
__device__ __align__(16) __nv_bfloat16 g_wgh[128 * 72],  g_wgl[128 * 72];     // gate_w1 N=64
__device__ __align__(16) __nv_bfloat16 g_whh[128 * 136], g_whl[128 * 136];    // head_w1
__device__ __align__(16) __nv_bfloat16 g_e1h[16 * 136],  g_e1l[16 * 136];     // edge_w1
__device__ __align__(16) __nv_bfloat16 g_e2h[128 * 136], g_e2l[128 * 136];    // edge_w2

// ---------------- helpers ----------------
__device__ __forceinline__ uint32_t smem_u32(const void* p) {
    uint32_t a;
    asm("{ .reg .u64 t; cvta.to.shared.u64 t, %1; cvt.u32.u64 %0, t; }" : "=r"(a) : "l"(p));
    return a;
}
__device__ __forceinline__ uint32_t bfpair(__nv_bfloat16 a, __nv_bfloat16 b) {
    __nv_bfloat162 v = __halves2bfloat162(a, b);
    return *reinterpret_cast<uint32_t*>(&v);
}
__device__ __forceinline__ void split1(float x, __nv_bfloat16& h, __nv_bfloat16& l) {
    h = __float2bfloat16(x);
    l = __float2bfloat16(x - __bfloat162float(h));
}

__device__ __forceinline__ void ldsm_x4(uint32_t* r, uint32_t addr) {
    asm volatile("ldmatrix.sync.aligned.m8n8.x4.shared.b16 {%0,%1,%2,%3}, [%4];"
                 : "=r"(r[0]), "=r"(r[1]), "=r"(r[2]), "=r"(r[3]) : "r"(addr));
}
__device__ __forceinline__ void ldsm_x4t(uint32_t* r, uint32_t addr) {
    asm volatile("ldmatrix.sync.aligned.m8n8.x4.trans.shared.b16 {%0,%1,%2,%3}, [%4];"
                 : "=r"(r[0]), "=r"(r[1]), "=r"(r[2]), "=r"(r[3]) : "r"(addr));
}
__device__ __forceinline__ void mma16816(float* d, const uint32_t* a, const uint32_t* b) {
    asm volatile(
        "mma.sync.aligned.m16n8k16.row.col.f32.bf16.bf16.f32 "
        "{%0,%1,%2,%3}, {%4,%5,%6,%7}, {%8,%9}, {%0,%1,%2,%3};"
        : "+f"(d[0]), "+f"(d[1]), "+f"(d[2]), "+f"(d[3])
        : "r"(a[0]), "r"(a[1]), "r"(a[2]), "r"(a[3]), "r"(b[0]), "r"(b[1]));
}

// ---------------- weight split+pad into scratch: W[K,N] fp32 -> [K][PB] bf16 hi/lo ----
__global__ void wconv_kernel(const float* __restrict__ W, int K, int N, int PB,
                             __nv_bfloat16* __restrict__ hi, __nv_bfloat16* __restrict__ lo) {
    int i = blockIdx.x * blockDim.x + threadIdx.x;
    if (i >= K * PB) return;
    int k = i / PB, n = i - k * PB;
    float x = (n < N) ? W[(size_t)k * N + n] : 0.f;
    __nv_bfloat16 h, l;
    split1(x, h, l);
    hi[i] = h;
    lo[i] = l;
}

// ---------------- tensor-core (mma.sync) GEMM: C = op(A[M,K] @ W[K,NC] + b) ----------
template <int K, int NC, bool RELU>
__global__ void __launch_bounds__(256) mma_gemm(
    const float* __restrict__ A, const __nv_bfloat16* __restrict__ Bhi,
    const __nv_bfloat16* __restrict__ Blo, const float* __restrict__ bias,
    float* __restrict__ C, int M) {
    constexpr int PA = K + 8;
    constexpr int PB = NC + 8;
    constexpr int NF = NC / 16;
    extern __shared__ __align__(16) char smc[];
    __nv_bfloat16* Ah = (__nv_bfloat16*)smc;
    __nv_bfloat16* Al = Ah + 128 * PA;
    __nv_bfloat16* Bh = Al + 128 * PA;
    __nv_bfloat16* Bl = Bh + K * PB;

    const int tid = threadIdx.x;
    const int lane = tid & 31, w = tid >> 5;
    const int wm = (w & 3) * 32;
    const int wn = (w >> 2) * (NC / 2);
    const int m0 = blockIdx.x * 128;

    {
        const float4* sh = (const float4*)Bhi;
        const float4* sl = (const float4*)Blo;
        float4* dh = (float4*)Bh;
        float4* dl = (float4*)Bl;
        for (int i = tid; i < K * PB / 8; i += 256) { dh[i] = sh[i]; dl[i] = sl[i]; }
    }
    {
        int r = tid >> 1, half = tid & 1;
        int gr = m0 + r;
        bool v = gr < M;
        const float4* a4 = (const float4*)(A + (size_t)gr * K) + half * (K / 8);
        __nv_bfloat16* th = Ah + r * PA + half * (K / 2);
        __nv_bfloat16* tl = Al + r * PA + half * (K / 2);
#pragma unroll
        for (int i = 0; i < K / 8; i++) {
            float4 x = v ? a4[i] : make_float4(0.f, 0.f, 0.f, 0.f);
            __nv_bfloat16 h0, h1, h2, h3, l0, l1, l2, l3;
            split1(x.x, h0, l0); split1(x.y, h1, l1);
            split1(x.z, h2, l2); split1(x.w, h3, l3);
            *(uint32_t*)(th + i * 4) = bfpair(h0, h1);
            *(uint32_t*)(th + i * 4 + 2) = bfpair(h2, h3);
            *(uint32_t*)(tl + i * 4) = bfpair(l0, l1);
            *(uint32_t*)(tl + i * 4 + 2) = bfpair(l2, l3);
        }
    }
    __syncthreads();

    float acc[2][NF][4];
#pragma unroll
    for (int i = 0; i < 2; i++)
#pragma unroll
        for (int j = 0; j < NF; j++)
#pragma unroll
            for (int q = 0; q < 4; q++) acc[i][j][q] = 0.f;

    const uint32_t Ahb = smem_u32(Ah), Alb = smem_u32(Al);
    const uint32_t Bhb = smem_u32(Bh), Blb = smem_u32(Bl);
    const int a_row = lane & 15, a_kof = (lane >> 4) << 3;
    const int b_mat = lane >> 3, b_r = lane & 7;
    const int b_krow = ((b_mat & 1) << 3) + b_r;
    const int b_ncol = (b_mat >> 1) << 3;

#pragma unroll
    for (int ks = 0; ks < K / 16; ks++) {
        const int k0 = ks * 16;
        uint32_t ahf[2][4], alf[2][4];
#pragma unroll
        for (int mi = 0; mi < 2; mi++) {
            uint32_t off = ((wm + mi * 16 + a_row) * PA + k0 + a_kof) * 2;
            ldsm_x4(ahf[mi], Ahb + off);
            ldsm_x4(alf[mi], Alb + off);
        }
#pragma unroll
        for (int np = 0; np < NF / 2; np++) {
            uint32_t off = ((k0 + b_krow) * PB + wn + np * 16 + b_ncol) * 2;
            uint32_t bhf[4], blf[4];
            ldsm_x4t(bhf, Bhb + off);
            ldsm_x4t(blf, Blb + off);
#pragma unroll
            for (int mi = 0; mi < 2; mi++) {
                mma16816(acc[mi][2 * np], ahf[mi], bhf);
                mma16816(acc[mi][2 * np], ahf[mi], blf);
                mma16816(acc[mi][2 * np], alf[mi], bhf);
                mma16816(acc[mi][2 * np + 1], ahf[mi], bhf + 2);
                mma16816(acc[mi][2 * np + 1], ahf[mi], blf + 2);
                mma16816(acc[mi][2 * np + 1], alf[mi], bhf + 2);
            }
        }
    }

    const int rbase = m0 + wm + (lane >> 2);
    const int cbase = wn + (lane & 3) * 2;
#pragma unroll
    for (int mi = 0; mi < 2; mi++) {
#pragma unroll
        for (int nj = 0; nj < NF; nj++) {
            int col = cbase + nj * 8;
            float b0 = bias[col], b1v = bias[col + 1];
#pragma unroll
            for (int hh = 0; hh < 2; hh++) {
                int row = rbase + mi * 16 + hh * 8;
                if (row < M) {
                    float v0 = acc[mi][nj][hh * 2 + 0] + b0;
                    float v1 = acc[mi][nj][hh * 2 + 1] + b1v;
                    if (RELU) { v0 = fmaxf(v0, 0.f); v1 = fmaxf(v1, 0.f); }
                    *(float2*)(C + (size_t)row * NC + col) = make_float2(v0, v1);
                }
            }
        }
    }
}

// ---------------- fused conv layer: h = relu(BN(relu(z@W1+b1)@W2+b2)) ----------------
__global__ void __launch_bounds__(256) conv_fused_kernel(
    const float* __restrict__ Z,
    const __nv_bfloat16* __restrict__ W1h, const __nv_bfloat16* __restrict__ W1l,
    const __nv_bfloat16* __restrict__ W2h, const __nv_bfloat16* __restrict__ W2l,
    const float* __restrict__ b1, const float* __restrict__ b2,
    const float* __restrict__ gamma, const float* __restrict__ beta,
    float* __restrict__ Hout, int M) {
    constexpr int PW = 136;
    extern __shared__ __align__(16) char smc[];
    __nv_bfloat16* Ah = (__nv_bfloat16*)smc;          // A / hidden, 128x136
    __nv_bfloat16* Al = Ah + 128 * PW;
    __nv_bfloat16* Q1h = Al + 128 * PW;
    __nv_bfloat16* Q1l = Q1h + 128 * PW;
    __nv_bfloat16* Q2h = Q1l + 128 * PW;
    __nv_bfloat16* Q2l = Q2h + 128 * PW;

    const int tid = threadIdx.x;
    const int lane = tid & 31, w = tid >> 5;
    const int wm = (w & 3) * 32;
    const int wn = (w >> 2) * 64;
    const int m0 = blockIdx.x * 128;

    // weights
    {
        const float4* s1h = (const float4*)W1h; const float4* s1l = (const float4*)W1l;
        const float4* s2h = (const float4*)W2h; const float4* s2l = (const float4*)W2l;
        float4* d1h = (float4*)Q1h; float4* d1l = (float4*)Q1l;
        float4* d2h = (float4*)Q2h; float4* d2l = (float4*)Q2l;
        for (int i = tid; i < 128 * PW / 8; i += 256) {
            d1h[i] = s1h[i]; d1l[i] = s1l[i];
            d2h[i] = s2h[i]; d2l[i] = s2l[i];
        }
    }
    // A: fp32 z -> split bf16
    {
        int r = tid >> 1, half = tid & 1;
        int gr = m0 + r;
        bool v = gr < M;
        const float4* a4 = (const float4*)(Z + (size_t)gr * 128) + half * 16;
        __nv_bfloat16* th = Ah + r * PW + half * 64;
        __nv_bfloat16* tl = Al + r * PW + half * 64;
#pragma unroll
        for (int i = 0; i < 16; i++) {
            float4 x = v ? a4[i] : make_float4(0.f, 0.f, 0.f, 0.f);
            __nv_bfloat16 h0, h1, h2, h3, l0, l1, l2, l3;
            split1(x.x, h0, l0); split1(x.y, h1, l1);
            split1(x.z, h2, l2); split1(x.w, h3, l3);
            *(uint32_t*)(th + i * 4) = bfpair(h0, h1);
            *(uint32_t*)(th + i * 4 + 2) = bfpair(h2, h3);
            *(uint32_t*)(tl + i * 4) = bfpair(l0, l1);
            *(uint32_t*)(tl + i * 4 + 2) = bfpair(l2, l3);
        }
    }
    __syncthreads();

    const uint32_t Ahb = smem_u32(Ah), Alb = smem_u32(Al);
    const uint32_t Q1hb = smem_u32(Q1h), Q1lb = smem_u32(Q1l);
    const uint32_t Q2hb = smem_u32(Q2h), Q2lb = smem_u32(Q2l);
    const int a_row = lane & 15, a_kof = (lane >> 4) << 3;
    const int b_mat = lane >> 3, b_r = lane & 7;
    const int b_krow = ((b_mat & 1) << 3) + b_r;
    const int b_ncol = (b_mat >> 1) << 3;
    const int frow = lane >> 2, fcol = (lane & 3) * 2;

    float acc[2][8][4];
#pragma unroll
    for (int i = 0; i < 2; i++)
#pragma unroll
        for (int j = 0; j < 8; j++)
#pragma unroll
            for (int q = 0; q < 4; q++) acc[i][j][q] = 0.f;

    // ---- phase 1: hidden = z @ W1, K=128 ----
#pragma unroll
    for (int ks = 0; ks < 8; ks++) {
        const int k0 = ks * 16;
        uint32_t ahf[2][4], alf[2][4];
#pragma unroll
        for (int mi = 0; mi < 2; mi++) {
            uint32_t off = ((wm + mi * 16 + a_row) * PW + k0 + a_kof) * 2;
            ldsm_x4(ahf[mi], Ahb + off);
            ldsm_x4(alf[mi], Alb + off);
        }
#pragma unroll
        for (int np = 0; np < 4; np++) {
            uint32_t off = ((k0 + b_krow) * PW + wn + np * 16 + b_ncol) * 2;
            uint32_t bhf[4], blf[4];
            ldsm_x4t(bhf, Q1hb + off);
            ldsm_x4t(blf, Q1lb + off);
#pragma unroll
            for (int mi = 0; mi < 2; mi++) {
                mma16816(acc[mi][2 * np], ahf[mi], bhf);
                mma16816(acc[mi][2 * np], ahf[mi], blf);
                mma16816(acc[mi][2 * np], alf[mi], bhf);
                mma16816(acc[mi][2 * np + 1], ahf[mi], bhf + 2);
                mma16816(acc[mi][2 * np + 1], ahf[mi], blf + 2);
                mma16816(acc[mi][2 * np + 1], alf[mi], bhf + 2);
            }
        }
    }
    __syncthreads();  // all warps done reading A before overwrite

    // relu(acc+b1) -> split -> back into Ah/Al
#pragma unroll
    for (int mi = 0; mi < 2; mi++) {
#pragma unroll
        for (int nj = 0; nj < 8; nj++) {
            int col = wn + nj * 8 + fcol;
            float c0 = b1[col], c1 = b1[col + 1];
#pragma unroll
            for (int hh = 0; hh < 2; hh++) {
                int row = wm + mi * 16 + hh * 8 + frow;
                float v0 = fmaxf(acc[mi][nj][hh * 2 + 0] + c0, 0.f);
                float v1 = fmaxf(acc[mi][nj][hh * 2 + 1] + c1, 0.f);
                __nv_bfloat16 h0, h1, l0, l1;
                split1(v0, h0, l0); split1(v1, h1, l1);
                *(uint32_t*)(Ah + row * PW + col) = bfpair(h0, h1);
                *(uint32_t*)(Al + row * PW + col) = bfpair(l0, l1);
            }
        }
    }
    __syncthreads();

    // ---- phase 2: out = hidden @ W2, K=128 ----
#pragma unroll
    for (int i = 0; i < 2; i++)
#pragma unroll
        for (int j = 0; j < 8; j++)
#pragma unroll
            for (int q = 0; q < 4; q++) acc[i][j][q] = 0.f;
#pragma unroll
    for (int ks = 0; ks < 8; ks++) {
        const int k0 = ks * 16;
        uint32_t ahf[2][4], alf[2][4];
#pragma unroll
        for (int mi = 0; mi < 2; mi++) {
            uint32_t off = ((wm + mi * 16 + a_row) * PW + k0 + a_kof) * 2;
            ldsm_x4(ahf[mi], Ahb + off);
            ldsm_x4(alf[mi], Alb + off);
        }
#pragma unroll
        for (int np = 0; np < 4; np++) {
            uint32_t off = ((k0 + b_krow) * PW + wn + np * 16 + b_ncol) * 2;
            uint32_t bhf[4], blf[4];
            ldsm_x4t(bhf, Q2hb + off);
            ldsm_x4t(blf, Q2lb + off);
#pragma unroll
            for (int mi = 0; mi < 2; mi++) {
                mma16816(acc[mi][2 * np], ahf[mi], bhf);
                mma16816(acc[mi][2 * np], ahf[mi], blf);
                mma16816(acc[mi][2 * np], alf[mi], bhf);
                mma16816(acc[mi][2 * np + 1], ahf[mi], bhf + 2);
                mma16816(acc[mi][2 * np + 1], ahf[mi], blf + 2);
                mma16816(acc[mi][2 * np + 1], alf[mi], bhf + 2);
            }
        }
    }

    // epilogue: BN + relu -> Hout
    const float bnsc = 0.99999500003749968f;  // 1/sqrt(1+1e-5)
#pragma unroll
    for (int mi = 0; mi < 2; mi++) {
#pragma unroll
        for (int nj = 0; nj < 8; nj++) {
            int col = wn + nj * 8 + fcol;
            float c0 = b2[col], c1 = b2[col + 1];
            float g0 = bnsc * gamma[col], g1 = bnsc * gamma[col + 1];
            float t0 = beta[col], t1 = beta[col + 1];
#pragma unroll
            for (int hh = 0; hh < 2; hh++) {
                int row = m0 + wm + mi * 16 + hh * 8 + frow;
                if (row < M) {
                    float v0 = fmaxf((acc[mi][nj][hh * 2 + 0] + c0) * g0 + t0, 0.f);
                    float v1 = fmaxf((acc[mi][nj][hh * 2 + 1] + c1) * g1 + t1, 0.f);
                    *(float2*)(Hout + (size_t)row * 128 + col) = make_float2(v0, v1);
                }
            }
        }
    }
}

// ---------------- fused edge encoder: e = bf16(relu(ea@W1+b1)@W2+b2) ----------------
__global__ void __launch_bounds__(256) edge_mma_kernel(
    const float* __restrict__ EA,
    const __nv_bfloat16* __restrict__ W1h, const __nv_bfloat16* __restrict__ W1l,
    const __nv_bfloat16* __restrict__ W2h, const __nv_bfloat16* __restrict__ W2l,
    const float* __restrict__ b1, const float* __restrict__ b2,
    __nv_bfloat16* __restrict__ Eout, int E) {
    constexpr int PA1 = 24;
    constexpr int PW = 136;
    extern __shared__ __align__(16) char smc[];
    __nv_bfloat16* A1h = (__nv_bfloat16*)smc;
    __nv_bfloat16* A1l = A1h + 128 * PA1;
    __nv_bfloat16* Q1h = A1l + 128 * PA1;
    __nv_bfloat16* Q1l = Q1h + 16 * PW;
    __nv_bfloat16* A2h = Q1l + 16 * PW;
    __nv_bfloat16* A2l = A2h + 128 * PW;
    __nv_bfloat16* Q2h = A2l + 128 * PW;
    __nv_bfloat16* Q2l = Q2h + 128 * PW;

    const int tid = threadIdx.x;
    const int lane = tid & 31, w = tid >> 5;
    const int wm = (w & 3) * 32;
    const int wn = (w >> 2) * 64;
    const int m0 = blockIdx.x * 128;

    {
        const float4* s1h = (const float4*)W1h; const float4* s1l = (const float4*)W1l;
        const float4* s2h = (const float4*)W2h; const float4* s2l = (const float4*)W2l;
        float4* d1h = (float4*)Q1h; float4* d1l = (float4*)Q1l;
        float4* d2h = (float4*)Q2h; float4* d2l = (float4*)Q2l;
        for (int i = tid; i < 16 * PW / 8; i += 256) { d1h[i] = s1h[i]; d1l[i] = s1l[i]; }
        for (int i = tid; i < 128 * PW / 8; i += 256) { d2h[i] = s2h[i]; d2l[i] = s2l[i]; }
    }
    {
        int r = tid >> 1, half = tid & 1;
        int ge = m0 + r;
        bool v = ge < E;
        const float4* a4 = (const float4*)(EA + (size_t)ge * 16) + half * 2;
        __nv_bfloat16* th = A1h + r * PA1 + half * 8;
        __nv_bfloat16* tl = A1l + r * PA1 + half * 8;
#pragma unroll
        for (int i = 0; i < 2; i++) {
            float4 x = v ? a4[i] : make_float4(0.f, 0.f, 0.f, 0.f);
            __nv_bfloat16 h0, h1, h2, h3, l0, l1, l2, l3;
            split1(x.x, h0, l0); split1(x.y, h1, l1);
            split1(x.z, h2, l2); split1(x.w, h3, l3);
            *(uint32_t*)(th + i * 4) = bfpair(h0, h1);
            *(uint32_t*)(th + i * 4 + 2) = bfpair(h2, h3);
            *(uint32_t*)(tl + i * 4) = bfpair(l0, l1);
            *(uint32_t*)(tl + i * 4 + 2) = bfpair(l2, l3);
        }
    }
    __syncthreads();

    const int a_row = lane & 15, a_kof = (lane >> 4) << 3;
    const int b_mat = lane >> 3, b_r = lane & 7;
    const int b_krow = ((b_mat & 1) << 3) + b_r;
    const int b_ncol = (b_mat >> 1) << 3;
    const int frow = lane >> 2, fcol = (lane & 3) * 2;

    float acc[2][8][4];
#pragma unroll
    for (int i = 0; i < 2; i++)
#pragma unroll
        for (int j = 0; j < 8; j++)
#pragma unroll
            for (int q = 0; q < 4; q++) acc[i][j][q] = 0.f;

    // phase 1: single k16 step
    {
        const uint32_t A1hb = smem_u32(A1h), A1lb = smem_u32(A1l);
        const uint32_t Q1hb = smem_u32(Q1h), Q1lb = smem_u32(Q1l);
        uint32_t ahf[2][4], alf[2][4];
#pragma unroll
        for (int mi = 0; mi < 2; mi++) {
            uint32_t off = ((wm + mi * 16 + a_row) * PA1 + a_kof) * 2;
            ldsm_x4(ahf[mi], A1hb + off);
            ldsm_x4(alf[mi], A1lb + off);
        }
#pragma unroll
        for (int np = 0; np < 4; np++) {
            uint32_t off = (b_krow * PW + wn + np * 16 + b_ncol) * 2;
            uint32_t bhf[4], blf[4];
            ldsm_x4t(bhf, Q1hb + off);
            ldsm_x4t(blf, Q1lb + off);
#pragma unroll
            for (int mi = 0; mi < 2; mi++) {
                mma16816(acc[mi][2 * np], ahf[mi], bhf);
                mma16816(acc[mi][2 * np], ahf[mi], blf);
                mma16816(acc[mi][2 * np], alf[mi], bhf);
                mma16816(acc[mi][2 * np + 1], ahf[mi], bhf + 2);
                mma16816(acc[mi][2 * np + 1], ahf[mi], blf + 2);
                mma16816(acc[mi][2 * np + 1], alf[mi], bhf + 2);
            }
        }
    }
#pragma unroll
    for (int mi = 0; mi < 2; mi++) {
#pragma unroll
        for (int nj = 0; nj < 8; nj++) {
            int col = wn + nj * 8 + fcol;
            float c0 = b1[col], c1 = b1[col + 1];
#pragma unroll
            for (int hh = 0; hh < 2; hh++) {
                int row = wm + mi * 16 + hh * 8 + frow;
                float v0 = fmaxf(acc[mi][nj][hh * 2 + 0] + c0, 0.f);
                float v1 = fmaxf(acc[mi][nj][hh * 2 + 1] + c1, 0.f);
                __nv_bfloat16 h0, h1, l0, l1;
                split1(v0, h0, l0); split1(v1, h1, l1);
                *(uint32_t*)(A2h + row * PW + col) = bfpair(h0, h1);
                *(uint32_t*)(A2l + row * PW + col) = bfpair(l0, l1);
            }
        }
    }
    __syncthreads();

    // phase 2: K=128
#pragma unroll
    for (int i = 0; i < 2; i++)
#pragma unroll
        for (int j = 0; j < 8; j++)
#pragma unroll
            for (int q = 0; q < 4; q++) acc[i][j][q] = 0.f;
    {
        const uint32_t A2hb = smem_u32(A2h), A2lb = smem_u32(A2l);
        const uint32_t Q2hb = smem_u32(Q2h), Q2lb = smem_u32(Q2l);
#pragma unroll
        for (int ks = 0; ks < 8; ks++) {
            const int k0 = ks * 16;
            uint32_t ahf[2][4], alf[2][4];
#pragma unroll
            for (int mi = 0; mi < 2; mi++) {
                uint32_t off = ((wm + mi * 16 + a_row) * PW + k0 + a_kof) * 2;
                ldsm_x4(ahf[mi], A2hb + off);
                ldsm_x4(alf[mi], A2lb + off);
            }
#pragma unroll
            for (int np = 0; np < 4; np++) {
                uint32_t off = ((k0 + b_krow) * PW + wn + np * 16 + b_ncol) * 2;
                uint32_t bhf[4], blf[4];
                ldsm_x4t(bhf, Q2hb + off);
                ldsm_x4t(blf, Q2lb + off);
#pragma unroll
                for (int mi = 0; mi < 2; mi++) {
                    mma16816(acc[mi][2 * np], ahf[mi], bhf);
                    mma16816(acc[mi][2 * np], ahf[mi], blf);
                    mma16816(acc[mi][2 * np], alf[mi], bhf);
                    mma16816(acc[mi][2 * np + 1], ahf[mi], bhf + 2);
                    mma16816(acc[mi][2 * np + 1], ahf[mi], blf + 2);
                    mma16816(acc[mi][2 * np + 1], alf[mi], bhf + 2);
                }
            }
        }
    }
    // epilogue: bf16 e
#pragma unroll
    for (int mi = 0; mi < 2; mi++) {
#pragma unroll
        for (int nj = 0; nj < 8; nj++) {
            int col = wn + nj * 8 + fcol;
            float c0 = b2[col], c1 = b2[col + 1];
#pragma unroll
            for (int hh = 0; hh < 2; hh++) {
                int row = m0 + wm + mi * 16 + hh * 8 + frow;
                if (row < E) {
                    __nv_bfloat16 o0 = __float2bfloat16(acc[mi][nj][hh * 2 + 0] + c0);
                    __nv_bfloat16 o1 = __float2bfloat16(acc[mi][nj][hh * 2 + 1] + c1);
                    *(uint32_t*)(Eout + (size_t)row * 128 + col) = bfpair(o0, o1);
                }
            }
        }
    }
}

// ---------------- CSR build ----------------
__global__ void hist_kernel(const int* __restrict__ ei, int* __restrict__ deg, int E) {
    int e = blockIdx.x * blockDim.x + threadIdx.x;
    if (e < E) atomicAdd(&deg[ei[E + e]], 1);
}

__global__ __launch_bounds__(1024) void scan_kernel(const int* __restrict__ deg,
                                                    int* __restrict__ off, int n) {
    __shared__ int s[1024];
    __shared__ int carry;
    int tid = threadIdx.x;
    if (tid == 0) carry = 0;
    __syncthreads();
    for (int base = 0; base < n; base += 1024) {
        int v = (base + tid < n) ? deg[base + tid] : 0;
        s[tid] = v;
        __syncthreads();
        for (int d = 1; d < 1024; d <<= 1) {
            int t = (tid >= d) ? s[tid - d] : 0;
            __syncthreads();
            if (tid >= d) s[tid] += t;
            __syncthreads();
        }
        if (base + tid < n) off[base + tid] = carry + s[tid] - v;
        __syncthreads();
        if (tid == 0) carry += s[1023];
        __syncthreads();
    }
}

__global__ void scatter_kernel(const int* __restrict__ ei, const int* __restrict__ off,
                               int* __restrict__ cur, int* __restrict__ eperm,
                               int* __restrict__ sperm, int E) {
    int e = blockIdx.x * blockDim.x + threadIdx.x;
    if (e >= E) return;
    int d = ei[E + e];
    int pos = off[d] + atomicAdd(&cur[d], 1);
    eperm[pos] = e;
    sperm[pos] = ei[e];
}

// ---------------- message + aggregate: z = h + sum relu(h[src]+e) (e bf16) ---------
__global__ __launch_bounds__(256) void aggregate_kernel(
    const float* __restrict__ h, const __nv_bfloat16* __restrict__ e,
    const int* __restrict__ off, const int* __restrict__ deg,
    const int* __restrict__ eperm, const int* __restrict__ sperm,
    float* __restrict__ z, int n) {
    int w = (blockIdx.x * blockDim.x + threadIdx.x) >> 5;
    int lane = threadIdx.x & 31;
    if (w >= n) return;
    const float4* h4 = reinterpret_cast<const float4*>(h);
    const uint2* e2 = reinterpret_cast<const uint2*>(e);  // 4 bf16 per uint2
    float4 acc = h4[w * 32 + lane];
    int s0 = off[w], d = deg[w];
    for (int j = s0; j < s0 + d; j++) {
        int ei = eperm[j];
        int si = sperm[j];
        uint2 ev = __ldcs(&e2[(size_t)ei * 32 + lane]);
        float4 hv = h4[si * 32 + lane];
        float2 f0 = __bfloat1622float2(*reinterpret_cast<__nv_bfloat162*>(&ev.x));
        float2 f1 = __bfloat1622float2(*reinterpret_cast<__nv_bfloat162*>(&ev.y));
        acc.x += fmaxf(f0.x + hv.x, 0.f);
        acc.y += fmaxf(f0.y + hv.y, 0.f);
        acc.z += fmaxf(f1.x + hv.z, 0.f);
        acc.w += fmaxf(f1.y + hv.w, 0.f);
    }
    reinterpret_cast<float4*>(z)[w * 32 + lane] = acc;
}

// ---------------- pooling ----------------
__global__ void gate2_kernel(const float* __restrict__ hid, const float* __restrict__ w2,
                             const float* __restrict__ b2, float* __restrict__ gate, int n) {
    int w = (blockIdx.x * blockDim.x + threadIdx.x) >> 5;
    int lane = threadIdx.x & 31;
    if (w >= n) return;
    float s = hid[w * 64 + lane] * w2[lane] + hid[w * 64 + 32 + lane] * w2[32 + lane];
#pragma unroll
    for (int o = 16; o > 0; o >>= 1) s += __shfl_down_sync(0xffffffffu, s, o);
    if (lane == 0) gate[w] = s + b2[0];
}

__device__ __forceinline__ unsigned f2ord(float f) {
    unsigned b = __float_as_uint(f);
    return (b & 0x80000000u) ? ~b : (b | 0x80000000u);
}
__device__ __forceinline__ float ord2f(unsigned k) {
    return __uint_as_float((k & 0x80000000u) ? (k & 0x7fffffffu) : ~k);
}

__global__ void smax_kernel(const float* __restrict__ gate, const int* __restrict__ batch,
                            unsigned* __restrict__ gmaxk, int n) {
    int i = blockIdx.x * blockDim.x + threadIdx.x;
    if (i < n) atomicMax(&gmaxk[batch[i]], f2ord(gate[i]));
}

__global__ void wexp_kernel(const float* __restrict__ gate, const int* __restrict__ batch,
                            const unsigned* __restrict__ gmaxk, float* __restrict__ wexp,
                            float* __restrict__ den, int n) {
    int i = blockIdx.x * blockDim.x + threadIdx.x;
    if (i >= n) return;
    float m = ord2f(gmaxk[batch[i]]);
    float w = expf(gate[i] - m);
    wexp[i] = w;
    atomicAdd(&den[batch[i]], w);
}

__global__ void pool_kernel(const float* __restrict__ h, const int* __restrict__ batch,
                            const float* __restrict__ wexp, const float* __restrict__ den,
                            float* __restrict__ pool, int n) {
    int w = (blockIdx.x * blockDim.x + threadIdx.x) >> 5;
    int lane = threadIdx.x & 31;
    if (w >= n) return;
    int b = batch[w];
    float alpha = wexp[w] / den[b];
#pragma unroll
    for (int j = 0; j < 4; j++) {
        int c = lane + 32 * j;
        atomicAdd(&pool[b * HH + c], alpha * h[(size_t)w * HH + c]);
    }
}

__global__ void head2_kernel(const float* __restrict__ ht, const float* __restrict__ w2,
                             const float* __restrict__ b2, float* __restrict__ out,
                             int G, int T) {
    int i = blockIdx.x * blockDim.x + threadIdx.x;
    if (i >= G * T) return;
    int g = i / T, t = i - g * T;
    float s = b2[t];
    for (int k = 0; k < HH; k++) s += ht[g * HH + k] * w2[k * T + t];
    out[i] = s;
}

// ---------------- launch ----------------
extern "C" void kernel_launch(void* const* d_in, const int* in_sizes, int n_in,
                              void* d_out, int out_size) {
    const float* x = (const float*)d_in[0];
    const float* edge_attr = (const float*)d_in[1];
    const float* node_w = (const float*)d_in[2];
    const float* node_b = (const float*)d_in[3];
    const float* edge_w1 = (const float*)d_in[4];
    const float* edge_b1 = (const float*)d_in[5];
    const float* edge_w2 = (const float*)d_in[6];
    const float* edge_b2 = (const float*)d_in[7];
    const float* conv_w1 = (const float*)d_in[8];
    const float* conv_b1 = (const float*)d_in[9];
    const float* conv_w2 = (const float*)d_in[10];
    const float* conv_b2 = (const float*)d_in[11];
    const float* bn_gamma = (const float*)d_in[12];
    const float* bn_beta = (const float*)d_in[13];
    const float* gate_w1 = (const float*)d_in[14];
    const float* gate_b1 = (const float*)d_in[15];
    const float* gate_w2 = (const float*)d_in[16];
    const float* gate_b2 = (const float*)d_in[17];
    const float* head_w1 = (const float*)d_in[18];
    const float* head_b1 = (const float*)d_in[19];
    const float* head_w2 = (const float*)d_in[20];
    const float* head_b2 = (const float*)d_in[21];
    const int* edge_index = (const int*)d_in[22];
    const int* batch = (const int*)d_in[23];

    const int N = in_sizes[0] / 64;
    const int E = in_sizes[22] / 2;
    const int T = 5;
    const int G = out_size / T;

    float *h, *z, *tb, *gate, *wexp, *den, *pool, *ht;
    __nv_bfloat16* e;
    int *deg, *off, *cur, *eperm, *sperm;
    unsigned* gmaxk;
    cudaGetSymbolAddress((void**)&h, g_h);
    cudaGetSymbolAddress((void**)&z, g_z);
    cudaGetSymbolAddress((void**)&tb, g_tb);
    cudaGetSymbolAddress((void**)&e, g_e);
    cudaGetSymbolAddress((void**)&deg, g_deg);
    cudaGetSymbolAddress((void**)&off, g_off);
    cudaGetSymbolAddress((void**)&cur, g_cur);
    cudaGetSymbolAddress((void**)&eperm, g_eperm);
    cudaGetSymbolAddress((void**)&sperm, g_sperm);
    cudaGetSymbolAddress((void**)&gate, g_gate);
    cudaGetSymbolAddress((void**)&wexp, g_wexp);
    cudaGetSymbolAddress((void**)&gmaxk, g_gmaxk);
    cudaGetSymbolAddress((void**)&den, g_den);
    cudaGetSymbolAddress((void**)&pool, g_pool);
    cudaGetSymbolAddress((void**)&ht, g_ht);

    __nv_bfloat16 *wnh, *wnl, *c1h, *c1l, *c2h, *c2l, *wgh, *wgl, *whh, *whl,
        *e1h, *e1l, *e2h, *e2l;
    cudaGetSymbolAddress((void**)&wnh, g_wnh); cudaGetSymbolAddress((void**)&wnl, g_wnl);
    cudaGetSymbolAddress((void**)&c1h, g_c1h); cudaGetSymbolAddress((void**)&c1l, g_c1l);
    cudaGetSymbolAddress((void**)&c2h, g_c2h); cudaGetSymbolAddress((void**)&c2l, g_c2l);
    cudaGetSymbolAddress((void**)&wgh, g_wgh); cudaGetSymbolAddress((void**)&wgl, g_wgl);
    cudaGetSymbolAddress((void**)&whh, g_whh); cudaGetSymbolAddress((void**)&whl, g_whl);
    cudaGetSymbolAddress((void**)&e1h, g_e1h); cudaGetSymbolAddress((void**)&e1l, g_e1l);
    cudaGetSymbolAddress((void**)&e2h, g_e2h); cudaGetSymbolAddress((void**)&e2l, g_e2l);

    // dynamic smem sizes (bytes)
    const int SM_N1 = (2 * 128 * 72 + 2 * 64 * 136) * 2;     // node: K=64,NC=128
    const int SM_G = (2 * 128 * 136 + 2 * 128 * 72) * 2;     // gate: K=128,NC=64
    const int SM_H = (2 * 128 * 136 + 2 * 128 * 136) * 2;    // head: K=128,NC=128
    const int SM_CONV = 6 * 128 * 136 * 2;                   // 208896
    const int SM_EDGE = (2 * 128 * 24 + 2 * 16 * 136 + 4 * 128 * 136) * 2;
    cudaFuncSetAttribute(mma_gemm<64, 128, false>, cudaFuncAttributeMaxDynamicSharedMemorySize, SM_N1);
    cudaFuncSetAttribute(mma_gemm<128, 64, true>, cudaFuncAttributeMaxDynamicSharedMemorySize, SM_G);
    cudaFuncSetAttribute(mma_gemm<128, 128, true>, cudaFuncAttributeMaxDynamicSharedMemorySize, SM_H);
    cudaFuncSetAttribute(conv_fused_kernel, cudaFuncAttributeMaxDynamicSharedMemorySize, SM_CONV);
    cudaFuncSetAttribute(edge_mma_kernel, cudaFuncAttributeMaxDynamicSharedMemorySize, SM_EDGE);

    // zero scratch
    cudaMemsetAsync(deg, 0, (size_t)N * 4, 0);
    cudaMemsetAsync(cur, 0, (size_t)N * 4, 0);
    cudaMemsetAsync(gmaxk, 0, (size_t)G * 4, 0);
    cudaMemsetAsync(den, 0, (size_t)G * 4, 0);
    cudaMemsetAsync(pool, 0, (size_t)G * HH * 4, 0);

    // weight prep (split + pad)
    wconv_kernel<<<(64 * 136 + 255) / 256, 256>>>(node_w, 64, 128, 136, wnh, wnl);
    for (int l = 0; l < 4; l++) {
        wconv_kernel<<<(128 * 136 + 255) / 256, 256>>>(
            conv_w1 + (size_t)l * 16384, 128, 128, 136,
            c1h + (size_t)l * 128 * 136, c1l + (size_t)l * 128 * 136);
        wconv_kernel<<<(128 * 136 + 255) / 256, 256>>>(
            conv_w2 + (size_t)l * 16384, 128, 128, 136,
            c2h + (size_t)l * 128 * 136, c2l + (size_t)l * 128 * 136);
    }
    wconv_kernel<<<(128 * 72 + 255) / 256, 256>>>(gate_w1, 128, 64, 72, wgh, wgl);
    wconv_kernel<<<(128 * 136 + 255) / 256, 256>>>(head_w1, 128, 128, 136, whh, whl);
    wconv_kernel<<<(16 * 136 + 255) / 256, 256>>>(edge_w1, 16, 128, 136, e1h, e1l);
    wconv_kernel<<<(128 * 136 + 255) / 256, 256>>>(edge_w2, 128, 128, 136, e2h, e2l);

    // CSR by dst
    hist_kernel<<<(E + 255) / 256, 256>>>(edge_index, deg, E);
    scan_kernel<<<1, 1024>>>(deg, off, N);
    scatter_kernel<<<(E + 255) / 256, 256>>>(edge_index, off, cur, eperm, sperm, E);

    // encoders
    mma_gemm<64, 128, false><<<(N + 127) / 128, 256, SM_N1>>>(x, wnh, wnl, node_b, h, N);
    edge_mma_kernel<<<(E + 127) / 128, 256, SM_EDGE>>>(
        edge_attr, e1h, e1l, e2h, e2l, edge_b1, edge_b2, e, E);

    // 4 GINE layers: aggregate -> fused 2-GEMM conv
    for (int l = 0; l < 4; l++) {
        aggregate_kernel<<<(N + 7) / 8, 256>>>(h, e, off, deg, eperm, sperm, z, N);
        conv_fused_kernel<<<(N + 127) / 128, 256, SM_CONV>>>(
            z, c1h + (size_t)l * 128 * 136, c1l + (size_t)l * 128 * 136,
            c2h + (size_t)l * 128 * 136, c2l + (size_t)l * 128 * 136,
            conv_b1 + l * HH, conv_b2 + l * HH,
            bn_gamma + l * HH, bn_beta + l * HH, h, N);
    }

    // gate MLP + segment softmax pooling
    mma_gemm<128, 64, true><<<(N + 127) / 128, 256, SM_G>>>(h, wgh, wgl, gate_b1, tb, N);
    gate2_kernel<<<(N + 7) / 8, 256>>>(tb, gate_w2, gate_b2, gate, N);
    smax_kernel<<<(N + 255) / 256, 256>>>(gate, batch, gmaxk, N);
    wexp_kernel<<<(N + 255) / 256, 256>>>(gate, batch, gmaxk, wexp, den, N);
    pool_kernel<<<(N + 7) / 8, 256>>>(h, batch, wexp, den, pool, N);

    // head
    mma_gemm<128, 128, true><<<(G + 127) / 128, 256, SM_H>>>(pool, whh, whl, head_b1, ht, G);
    head2_kernel<<<(G * T + 255) / 256, 256>>>(ht, head_w2, head_b2, (float*)d_out, G, T);
}

// round 9
// speedup vs baseline: 3.2658x; 1.3597x over previous
#include <cuda_runtime.h>
#include <cuda_bf16.h>
#include <cstdint>

#define NN 50000
#define EE 640000
#define GGR 256
#define HH 128

// ---------------- scratch (device globals; no allocs allowed) ----------------
__device__ __align__(16) float g_h[NN * HH];
__device__ __align__(16) __nv_bfloat16 g_hb[NN * HH];   // bf16 shadow of h
__device__ __align__(16) float g_z[NN * HH];
__device__ __align__(16) float g_tb[NN * HH];
__device__ __align__(16) __nv_bfloat16 g_e[(size_t)EE * HH];
__device__ int g_deg[NN];
__device__ int g_off[NN];
__device__ int g_cur[NN];
__device__ int g_bsum[64];
__device__ int g_eperm[EE];
__device__ int g_sperm[EE];
__device__ float g_gate[NN];
__device__ float g_wexp[NN];
__device__ unsigned g_gmaxk[GGR];
__device__ float g_den[GGR];
__device__ __align__(16) float g_pool[GGR * HH];
__device__ __align__(16) float g_ht[GGR * HH];

// split-bf16 weights, [K][N] row-major with padded pitch PB=N+8, hi/lo
__device__ __align__(16) __nv_bfloat16 g_wnh[64 * 136],  g_wnl[64 * 136];
__device__ __align__(16) __nv_bfloat16 g_c1h[4 * 128 * 136], g_c1l[4 * 128 * 136];
__device__ __align__(16) __nv_bfloat16 g_c2h[4 * 128 * 136], g_c2l[4 * 128 * 136];
__device__ __align__(16) __nv_bfloat16 g_wgh[128 * 72],  g_wgl[128 * 72];
__device__ __align__(16) __nv_bfloat16 g_whh[128 * 136], g_whl[128 * 136];
__device__ __align__(16) __nv_bfloat16 g_e1h[16 * 136],  g_e1l[16 * 136];
__device__ __align__(16) __nv_bfloat16 g_e2h[128 * 136], g_e2l[128 * 136];

// ---------------- helpers ----------------
__device__ __forceinline__ uint32_t smem_u32(const void* p) {
    uint32_t a;
    asm("{ .reg .u64 t; cvta.to.shared.u64 t, %1; cvt.u32.u64 %0, t; }" : "=r"(a) : "l"(p));
    return a;
}
__device__ __forceinline__ uint32_t bfpair(__nv_bfloat16 a, __nv_bfloat16 b) {
    __nv_bfloat162 v = __halves2bfloat162(a, b);
    return *reinterpret_cast<uint32_t*>(&v);
}
__device__ __forceinline__ void split1(float x, __nv_bfloat16& h, __nv_bfloat16& l) {
    h = __float2bfloat16(x);
    l = __float2bfloat16(x - __bfloat162float(h));
}

__device__ __forceinline__ void ldsm_x4(uint32_t* r, uint32_t addr) {
    asm volatile("ldmatrix.sync.aligned.m8n8.x4.shared.b16 {%0,%1,%2,%3}, [%4];"
                 : "=r"(r[0]), "=r"(r[1]), "=r"(r[2]), "=r"(r[3]) : "r"(addr));
}
__device__ __forceinline__ void ldsm_x4t(uint32_t* r, uint32_t addr) {
    asm volatile("ldmatrix.sync.aligned.m8n8.x4.trans.shared.b16 {%0,%1,%2,%3}, [%4];"
                 : "=r"(r[0]), "=r"(r[1]), "=r"(r[2]), "=r"(r[3]) : "r"(addr));
}
__device__ __forceinline__ void mma16816(float* d, const uint32_t* a, const uint32_t* b) {
    asm volatile(
        "mma.sync.aligned.m16n8k16.row.col.f32.bf16.bf16.f32 "
        "{%0,%1,%2,%3}, {%4,%5,%6,%7}, {%8,%9}, {%0,%1,%2,%3};"
        : "+f"(d[0]), "+f"(d[1]), "+f"(d[2]), "+f"(d[3])
        : "r"(a[0]), "r"(a[1]), "r"(a[2]), "r"(a[3]), "r"(b[0]), "r"(b[1]));
}

// ---------------- weight split+pad: W[K,N] fp32 -> [K][PB] bf16 hi/lo ----------------
__global__ void wconv_kernel(const float* __restrict__ W, int K, int N, int PB,
                             __nv_bfloat16* __restrict__ hi, __nv_bfloat16* __restrict__ lo) {
    int i = blockIdx.x * blockDim.x + threadIdx.x;
    if (i >= K * PB) return;
    int k = i / PB, n = i - k * PB;
    float x = (n < N) ? W[(size_t)k * N + n] : 0.f;
    __nv_bfloat16 h, l;
    split1(x, h, l);
    hi[i] = h;
    lo[i] = l;
}

// ---------------- tensor-core GEMM: C = op(A[M,K] @ W[K,NC] + b) -------------------
template <int K, int NC, bool RELU, bool BF16OUT>
__global__ void __launch_bounds__(256) mma_gemm(
    const float* __restrict__ A, const __nv_bfloat16* __restrict__ Bhi,
    const __nv_bfloat16* __restrict__ Blo, const float* __restrict__ bias,
    float* __restrict__ C, __nv_bfloat16* __restrict__ Cb, int M) {
    constexpr int PA = K + 8;
    constexpr int PB = NC + 8;
    constexpr int NF = NC / 16;
    extern __shared__ __align__(16) char smc[];
    __nv_bfloat16* Ah = (__nv_bfloat16*)smc;
    __nv_bfloat16* Al = Ah + 128 * PA;
    __nv_bfloat16* Bh = Al + 128 * PA;
    __nv_bfloat16* Bl = Bh + K * PB;

    const int tid = threadIdx.x;
    const int lane = tid & 31, w = tid >> 5;
    const int wm = (w & 3) * 32;
    const int wn = (w >> 2) * (NC / 2);
    const int m0 = blockIdx.x * 128;

    {
        const float4* sh = (const float4*)Bhi;
        const float4* sl = (const float4*)Blo;
        float4* dh = (float4*)Bh;
        float4* dl = (float4*)Bl;
        for (int i = tid; i < K * PB / 8; i += 256) { dh[i] = sh[i]; dl[i] = sl[i]; }
    }
    {
        int r = tid >> 1, half = tid & 1;
        int gr = m0 + r;
        bool v = gr < M;
        const float4* a4 = (const float4*)(A + (size_t)gr * K) + half * (K / 8);
        __nv_bfloat16* th = Ah + r * PA + half * (K / 2);
        __nv_bfloat16* tl = Al + r * PA + half * (K / 2);
#pragma unroll
        for (int i = 0; i < K / 8; i++) {
            float4 x = v ? a4[i] : make_float4(0.f, 0.f, 0.f, 0.f);
            __nv_bfloat16 h0, h1, h2, h3, l0, l1, l2, l3;
            split1(x.x, h0, l0); split1(x.y, h1, l1);
            split1(x.z, h2, l2); split1(x.w, h3, l3);
            *(uint32_t*)(th + i * 4) = bfpair(h0, h1);
            *(uint32_t*)(th + i * 4 + 2) = bfpair(h2, h3);
            *(uint32_t*)(tl + i * 4) = bfpair(l0, l1);
            *(uint32_t*)(tl + i * 4 + 2) = bfpair(l2, l3);
        }
    }
    __syncthreads();

    float acc[2][NF][4];
#pragma unroll
    for (int i = 0; i < 2; i++)
#pragma unroll
        for (int j = 0; j < NF; j++)
#pragma unroll
            for (int q = 0; q < 4; q++) acc[i][j][q] = 0.f;

    const uint32_t Ahb = smem_u32(Ah), Alb = smem_u32(Al);
    const uint32_t Bhb = smem_u32(Bh), Blb = smem_u32(Bl);
    const int a_row = lane & 15, a_kof = (lane >> 4) << 3;
    const int b_mat = lane >> 3, b_r = lane & 7;
    const int b_krow = ((b_mat & 1) << 3) + b_r;
    const int b_ncol = (b_mat >> 1) << 3;

#pragma unroll
    for (int ks = 0; ks < K / 16; ks++) {
        const int k0 = ks * 16;
        uint32_t ahf[2][4], alf[2][4];
#pragma unroll
        for (int mi = 0; mi < 2; mi++) {
            uint32_t off = ((wm + mi * 16 + a_row) * PA + k0 + a_kof) * 2;
            ldsm_x4(ahf[mi], Ahb + off);
            ldsm_x4(alf[mi], Alb + off);
        }
#pragma unroll
        for (int np = 0; np < NF / 2; np++) {
            uint32_t off = ((k0 + b_krow) * PB + wn + np * 16 + b_ncol) * 2;
            uint32_t bhf[4], blf[4];
            ldsm_x4t(bhf, Bhb + off);
            ldsm_x4t(blf, Blb + off);
#pragma unroll
            for (int mi = 0; mi < 2; mi++) {
                mma16816(acc[mi][2 * np], ahf[mi], bhf);
                mma16816(acc[mi][2 * np], ahf[mi], blf);
                mma16816(acc[mi][2 * np], alf[mi], bhf);
                mma16816(acc[mi][2 * np + 1], ahf[mi], bhf + 2);
                mma16816(acc[mi][2 * np + 1], ahf[mi], blf + 2);
                mma16816(acc[mi][2 * np + 1], alf[mi], bhf + 2);
            }
        }
    }

    const int rbase = m0 + wm + (lane >> 2);
    const int cbase = wn + (lane & 3) * 2;
#pragma unroll
    for (int mi = 0; mi < 2; mi++) {
#pragma unroll
        for (int nj = 0; nj < NF; nj++) {
            int col = cbase + nj * 8;
            float b0 = bias[col], b1v = bias[col + 1];
#pragma unroll
            for (int hh = 0; hh < 2; hh++) {
                int row = rbase + mi * 16 + hh * 8;
                if (row < M) {
                    float v0 = acc[mi][nj][hh * 2 + 0] + b0;
                    float v1 = acc[mi][nj][hh * 2 + 1] + b1v;
                    if (RELU) { v0 = fmaxf(v0, 0.f); v1 = fmaxf(v1, 0.f); }
                    *(float2*)(C + (size_t)row * NC + col) = make_float2(v0, v1);
                    if (BF16OUT)
                        *(uint32_t*)(Cb + (size_t)row * NC + col) =
                            bfpair(__float2bfloat16(v0), __float2bfloat16(v1));
                }
            }
        }
    }
}

// ---------------- fused conv layer: h = relu(BN(relu(z@W1+b1)@W2+b2)) --------------
__global__ void __launch_bounds__(256) conv_fused_kernel(
    const float* __restrict__ Z,
    const __nv_bfloat16* __restrict__ W1h, const __nv_bfloat16* __restrict__ W1l,
    const __nv_bfloat16* __restrict__ W2h, const __nv_bfloat16* __restrict__ W2l,
    const float* __restrict__ b1, const float* __restrict__ b2,
    const float* __restrict__ gamma, const float* __restrict__ beta,
    float* __restrict__ Hout, __nv_bfloat16* __restrict__ Hb, int M) {
    constexpr int PW = 136;
    extern __shared__ __align__(16) char smc[];
    __nv_bfloat16* Ah = (__nv_bfloat16*)smc;
    __nv_bfloat16* Al = Ah + 128 * PW;
    __nv_bfloat16* Q1h = Al + 128 * PW;
    __nv_bfloat16* Q1l = Q1h + 128 * PW;
    __nv_bfloat16* Q2h = Q1l + 128 * PW;
    __nv_bfloat16* Q2l = Q2h + 128 * PW;

    const int tid = threadIdx.x;
    const int lane = tid & 31, w = tid >> 5;
    const int wm = (w & 3) * 32;
    const int wn = (w >> 2) * 64;
    const int m0 = blockIdx.x * 128;

    {
        const float4* s1h = (const float4*)W1h; const float4* s1l = (const float4*)W1l;
        const float4* s2h = (const float4*)W2h; const float4* s2l = (const float4*)W2l;
        float4* d1h = (float4*)Q1h; float4* d1l = (float4*)Q1l;
        float4* d2h = (float4*)Q2h; float4* d2l = (float4*)Q2l;
        for (int i = tid; i < 128 * PW / 8; i += 256) {
            d1h[i] = s1h[i]; d1l[i] = s1l[i];
            d2h[i] = s2h[i]; d2l[i] = s2l[i];
        }
    }
    {
        int r = tid >> 1, half = tid & 1;
        int gr = m0 + r;
        bool v = gr < M;
        const float4* a4 = (const float4*)(Z + (size_t)gr * 128) + half * 16;
        __nv_bfloat16* th = Ah + r * PW + half * 64;
        __nv_bfloat16* tl = Al + r * PW + half * 64;
#pragma unroll
        for (int i = 0; i < 16; i++) {
            float4 x = v ? a4[i] : make_float4(0.f, 0.f, 0.f, 0.f);
            __nv_bfloat16 h0, h1, h2, h3, l0, l1, l2, l3;
            split1(x.x, h0, l0); split1(x.y, h1, l1);
            split1(x.z, h2, l2); split1(x.w, h3, l3);
            *(uint32_t*)(th + i * 4) = bfpair(h0, h1);
            *(uint32_t*)(th + i * 4 + 2) = bfpair(h2, h3);
            *(uint32_t*)(tl + i * 4) = bfpair(l0, l1);
            *(uint32_t*)(tl + i * 4 + 2) = bfpair(l2, l3);
        }
    }
    __syncthreads();

    const uint32_t Ahb = smem_u32(Ah), Alb = smem_u32(Al);
    const uint32_t Q1hb = smem_u32(Q1h), Q1lb = smem_u32(Q1l);
    const uint32_t Q2hb = smem_u32(Q2h), Q2lb = smem_u32(Q2l);
    const int a_row = lane & 15, a_kof = (lane >> 4) << 3;
    const int b_mat = lane >> 3, b_r = lane & 7;
    const int b_krow = ((b_mat & 1) << 3) + b_r;
    const int b_ncol = (b_mat >> 1) << 3;
    const int frow = lane >> 2, fcol = (lane & 3) * 2;

    float acc[2][8][4];
#pragma unroll
    for (int i = 0; i < 2; i++)
#pragma unroll
        for (int j = 0; j < 8; j++)
#pragma unroll
            for (int q = 0; q < 4; q++) acc[i][j][q] = 0.f;

#pragma unroll
    for (int ks = 0; ks < 8; ks++) {
        const int k0 = ks * 16;
        uint32_t ahf[2][4], alf[2][4];
#pragma unroll
        for (int mi = 0; mi < 2; mi++) {
            uint32_t off = ((wm + mi * 16 + a_row) * PW + k0 + a_kof) * 2;
            ldsm_x4(ahf[mi], Ahb + off);
            ldsm_x4(alf[mi], Alb + off);
        }
#pragma unroll
        for (int np = 0; np < 4; np++) {
            uint32_t off = ((k0 + b_krow) * PW + wn + np * 16 + b_ncol) * 2;
            uint32_t bhf[4], blf[4];
            ldsm_x4t(bhf, Q1hb + off);
            ldsm_x4t(blf, Q1lb + off);
#pragma unroll
            for (int mi = 0; mi < 2; mi++) {
                mma16816(acc[mi][2 * np], ahf[mi], bhf);
                mma16816(acc[mi][2 * np], ahf[mi], blf);
                mma16816(acc[mi][2 * np], alf[mi], bhf);
                mma16816(acc[mi][2 * np + 1], ahf[mi], bhf + 2);
                mma16816(acc[mi][2 * np + 1], ahf[mi], blf + 2);
                mma16816(acc[mi][2 * np + 1], alf[mi], bhf + 2);
            }
        }
    }
    __syncthreads();

#pragma unroll
    for (int mi = 0; mi < 2; mi++) {
#pragma unroll
        for (int nj = 0; nj < 8; nj++) {
            int col = wn + nj * 8 + fcol;
            float c0 = b1[col], c1 = b1[col + 1];
#pragma unroll
            for (int hh = 0; hh < 2; hh++) {
                int row = wm + mi * 16 + hh * 8 + frow;
                float v0 = fmaxf(acc[mi][nj][hh * 2 + 0] + c0, 0.f);
                float v1 = fmaxf(acc[mi][nj][hh * 2 + 1] + c1, 0.f);
                __nv_bfloat16 h0, h1, l0, l1;
                split1(v0, h0, l0); split1(v1, h1, l1);
                *(uint32_t*)(Ah + row * PW + col) = bfpair(h0, h1);
                *(uint32_t*)(Al + row * PW + col) = bfpair(l0, l1);
            }
        }
    }
    __syncthreads();

#pragma unroll
    for (int i = 0; i < 2; i++)
#pragma unroll
        for (int j = 0; j < 8; j++)
#pragma unroll
            for (int q = 0; q < 4; q++) acc[i][j][q] = 0.f;
#pragma unroll
    for (int ks = 0; ks < 8; ks++) {
        const int k0 = ks * 16;
        uint32_t ahf[2][4], alf[2][4];
#pragma unroll
        for (int mi = 0; mi < 2; mi++) {
            uint32_t off = ((wm + mi * 16 + a_row) * PW + k0 + a_kof) * 2;
            ldsm_x4(ahf[mi], Ahb + off);
            ldsm_x4(alf[mi], Alb + off);
        }
#pragma unroll
        for (int np = 0; np < 4; np++) {
            uint32_t off = ((k0 + b_krow) * PW + wn + np * 16 + b_ncol) * 2;
            uint32_t bhf[4], blf[4];
            ldsm_x4t(bhf, Q2hb + off);
            ldsm_x4t(blf, Q2lb + off);
#pragma unroll
            for (int mi = 0; mi < 2; mi++) {
                mma16816(acc[mi][2 * np], ahf[mi], bhf);
                mma16816(acc[mi][2 * np], ahf[mi], blf);
                mma16816(acc[mi][2 * np], alf[mi], bhf);
                mma16816(acc[mi][2 * np + 1], ahf[mi], bhf + 2);
                mma16816(acc[mi][2 * np + 1], ahf[mi], blf + 2);
                mma16816(acc[mi][2 * np + 1], alf[mi], bhf + 2);
            }
        }
    }

    const float bnsc = 0.99999500003749968f;
#pragma unroll
    for (int mi = 0; mi < 2; mi++) {
#pragma unroll
        for (int nj = 0; nj < 8; nj++) {
            int col = wn + nj * 8 + fcol;
            float c0 = b2[col], c1 = b2[col + 1];
            float g0 = bnsc * gamma[col], g1 = bnsc * gamma[col + 1];
            float t0 = beta[col], t1 = beta[col + 1];
#pragma unroll
            for (int hh = 0; hh < 2; hh++) {
                int row = m0 + wm + mi * 16 + hh * 8 + frow;
                if (row < M) {
                    float v0 = fmaxf((acc[mi][nj][hh * 2 + 0] + c0) * g0 + t0, 0.f);
                    float v1 = fmaxf((acc[mi][nj][hh * 2 + 1] + c1) * g1 + t1, 0.f);
                    *(float2*)(Hout + (size_t)row * 128 + col) = make_float2(v0, v1);
                    *(uint32_t*)(Hb + (size_t)row * 128 + col) =
                        bfpair(__float2bfloat16(v0), __float2bfloat16(v1));
                }
            }
        }
    }
}

// ---------------- fused edge encoder (hi-only bf16): e = bf16(relu(ea@W1+b1)@W2+b2) -
__global__ void __launch_bounds__(256) edge_mma_kernel(
    const float* __restrict__ EA,
    const __nv_bfloat16* __restrict__ W1h, const __nv_bfloat16* __restrict__ W2h,
    const float* __restrict__ b1, const float* __restrict__ b2,
    __nv_bfloat16* __restrict__ Eout, int E) {
    constexpr int PA1 = 24;
    constexpr int PW = 136;
    extern __shared__ __align__(16) char smc[];
    __nv_bfloat16* A1 = (__nv_bfloat16*)smc;   // 128*24
    __nv_bfloat16* Q1 = A1 + 128 * PA1;        // 16*136
    __nv_bfloat16* A2 = Q1 + 16 * PW;          // 128*136
    __nv_bfloat16* Q2 = A2 + 128 * PW;         // 128*136

    const int tid = threadIdx.x;
    const int lane = tid & 31, w = tid >> 5;
    const int wm = (w & 3) * 32;
    const int wn = (w >> 2) * 64;
    const int m0 = blockIdx.x * 128;

    {
        const float4* s1 = (const float4*)W1h;
        const float4* s2 = (const float4*)W2h;
        float4* d1 = (float4*)Q1;
        float4* d2 = (float4*)Q2;
        for (int i = tid; i < 16 * PW / 8; i += 256) d1[i] = s1[i];
        for (int i = tid; i < 128 * PW / 8; i += 256) d2[i] = s2[i];
    }
    {
        int r = tid >> 1, half = tid & 1;
        int ge = m0 + r;
        bool v = ge < E;
        const float4* a4 = (const float4*)(EA + (size_t)ge * 16) + half * 2;
        __nv_bfloat16* th = A1 + r * PA1 + half * 8;
#pragma unroll
        for (int i = 0; i < 2; i++) {
            float4 x = v ? a4[i] : make_float4(0.f, 0.f, 0.f, 0.f);
            *(uint32_t*)(th + i * 4) = bfpair(__float2bfloat16(x.x), __float2bfloat16(x.y));
            *(uint32_t*)(th + i * 4 + 2) = bfpair(__float2bfloat16(x.z), __float2bfloat16(x.w));
        }
    }
    __syncthreads();

    const int a_row = lane & 15, a_kof = (lane >> 4) << 3;
    const int b_mat = lane >> 3, b_r = lane & 7;
    const int b_krow = ((b_mat & 1) << 3) + b_r;
    const int b_ncol = (b_mat >> 1) << 3;
    const int frow = lane >> 2, fcol = (lane & 3) * 2;

    float acc[2][8][4];
#pragma unroll
    for (int i = 0; i < 2; i++)
#pragma unroll
        for (int j = 0; j < 8; j++)
#pragma unroll
            for (int q = 0; q < 4; q++) acc[i][j][q] = 0.f;

    // phase 1: hidden = ea @ W1 (single k16 step, hi-only)
    {
        const uint32_t A1b = smem_u32(A1), Q1b = smem_u32(Q1);
        uint32_t af[2][4];
#pragma unroll
        for (int mi = 0; mi < 2; mi++)
            ldsm_x4(af[mi], A1b + ((wm + mi * 16 + a_row) * PA1 + a_kof) * 2);
#pragma unroll
        for (int np = 0; np < 4; np++) {
            uint32_t bf[4];
            ldsm_x4t(bf, Q1b + (b_krow * PW + wn + np * 16 + b_ncol) * 2);
#pragma unroll
            for (int mi = 0; mi < 2; mi++) {
                mma16816(acc[mi][2 * np], af[mi], bf);
                mma16816(acc[mi][2 * np + 1], af[mi], bf + 2);
            }
        }
    }
#pragma unroll
    for (int mi = 0; mi < 2; mi++) {
#pragma unroll
        for (int nj = 0; nj < 8; nj++) {
            int col = wn + nj * 8 + fcol;
            float c0 = b1[col], c1 = b1[col + 1];
#pragma unroll
            for (int hh = 0; hh < 2; hh++) {
                int row = wm + mi * 16 + hh * 8 + frow;
                float v0 = fmaxf(acc[mi][nj][hh * 2 + 0] + c0, 0.f);
                float v1 = fmaxf(acc[mi][nj][hh * 2 + 1] + c1, 0.f);
                *(uint32_t*)(A2 + row * PW + col) =
                    bfpair(__float2bfloat16(v0), __float2bfloat16(v1));
            }
        }
    }
    __syncthreads();

    // phase 2: e = hidden @ W2, K=128, hi-only
#pragma unroll
    for (int i = 0; i < 2; i++)
#pragma unroll
        for (int j = 0; j < 8; j++)
#pragma unroll
            for (int q = 0; q < 4; q++) acc[i][j][q] = 0.f;
    {
        const uint32_t A2b = smem_u32(A2), Q2b = smem_u32(Q2);
#pragma unroll
        for (int ks = 0; ks < 8; ks++) {
            const int k0 = ks * 16;
            uint32_t af[2][4];
#pragma unroll
            for (int mi = 0; mi < 2; mi++)
                ldsm_x4(af[mi], A2b + ((wm + mi * 16 + a_row) * PW + k0 + a_kof) * 2);
#pragma unroll
            for (int np = 0; np < 4; np++) {
                uint32_t bf[4];
                ldsm_x4t(bf, Q2b + ((k0 + b_krow) * PW + wn + np * 16 + b_ncol) * 2);
#pragma unroll
                for (int mi = 0; mi < 2; mi++) {
                    mma16816(acc[mi][2 * np], af[mi], bf);
                    mma16816(acc[mi][2 * np + 1], af[mi], bf + 2);
                }
            }
        }
    }
#pragma unroll
    for (int mi = 0; mi < 2; mi++) {
#pragma unroll
        for (int nj = 0; nj < 8; nj++) {
            int col = wn + nj * 8 + fcol;
            float c0 = b2[col], c1 = b2[col + 1];
#pragma unroll
            for (int hh = 0; hh < 2; hh++) {
                int row = m0 + wm + mi * 16 + hh * 8 + frow;
                if (row < E) {
                    *(uint32_t*)(Eout + (size_t)row * 128 + col) =
                        bfpair(__float2bfloat16(acc[mi][nj][hh * 2 + 0] + c0),
                               __float2bfloat16(acc[mi][nj][hh * 2 + 1] + c1));
                }
            }
        }
    }
}

// ---------------- CSR build ----------------
__global__ void hist_kernel(const int* __restrict__ ei, int* __restrict__ deg, int E) {
    int e = blockIdx.x * blockDim.x + threadIdx.x;
    if (e < E) atomicAdd(&deg[ei[E + e]], 1);
}

// multi-block exclusive scan: phase 1 per-block scan + block sums
__global__ __launch_bounds__(1024) void scan1_kernel(const int* __restrict__ deg,
                                                     int* __restrict__ off,
                                                     int* __restrict__ bsum, int n) {
    __shared__ int s[1024];
    int tid = threadIdx.x;
    int gi = blockIdx.x * 1024 + tid;
    int v = (gi < n) ? deg[gi] : 0;
    s[tid] = v;
    __syncthreads();
    for (int d = 1; d < 1024; d <<= 1) {
        int t = (tid >= d) ? s[tid - d] : 0;
        __syncthreads();
        if (tid >= d) s[tid] += t;
        __syncthreads();
    }
    if (gi < n) off[gi] = s[tid] - v;
    if (tid == 1023) bsum[blockIdx.x] = s[1023];
}

__global__ void scan2_kernel(int* __restrict__ bsum, int nb) {
    // single warp-wide serial scan (nb <= 64)
    if (threadIdx.x == 0) {
        int acc = 0;
        for (int i = 0; i < nb; i++) {
            int v = bsum[i];
            bsum[i] = acc;
            acc += v;
        }
    }
}

__global__ void scan3_kernel(int* __restrict__ off, const int* __restrict__ bsum, int n) {
    int i = blockIdx.x * blockDim.x + threadIdx.x;
    if (i < n) off[i] += bsum[i >> 10];
}

__global__ void scatter_kernel(const int* __restrict__ ei, const int* __restrict__ off,
                               int* __restrict__ cur, int* __restrict__ eperm,
                               int* __restrict__ sperm, int E) {
    int e = blockIdx.x * blockDim.x + threadIdx.x;
    if (e >= E) return;
    int d = ei[E + e];
    int pos = off[d] + atomicAdd(&cur[d], 1);
    eperm[pos] = e;
    sperm[pos] = ei[e];
}

// ---------------- message + aggregate: z = h + sum relu(hb[src]+e) ----------------
__global__ __launch_bounds__(256) void aggregate_kernel(
    const float* __restrict__ h, const __nv_bfloat16* __restrict__ hb,
    const __nv_bfloat16* __restrict__ e,
    const int* __restrict__ off, const int* __restrict__ deg,
    const int* __restrict__ eperm, const int* __restrict__ sperm,
    float* __restrict__ z, int n) {
    int w = (blockIdx.x * blockDim.x + threadIdx.x) >> 5;
    int lane = threadIdx.x & 31;
    if (w >= n) return;
    const float4* h4 = reinterpret_cast<const float4*>(h);
    const uint2* e2 = reinterpret_cast<const uint2*>(e);
    const uint2* hb2 = reinterpret_cast<const uint2*>(hb);
    float4 acc = h4[w * 32 + lane];
    int s0 = off[w], d = deg[w];
    int j = s0;
    const int jend = s0 + d;
    for (; j + 1 < jend; j += 2) {
        int ei0 = eperm[j], si0 = sperm[j];
        int ei1 = eperm[j + 1], si1 = sperm[j + 1];
        uint2 ev0 = __ldcs(&e2[(size_t)ei0 * 32 + lane]);
        uint2 hv0 = hb2[(size_t)si0 * 32 + lane];
        uint2 ev1 = __ldcs(&e2[(size_t)ei1 * 32 + lane]);
        uint2 hv1 = hb2[(size_t)si1 * 32 + lane];
        float2 e00 = __bfloat1622float2(*reinterpret_cast<__nv_bfloat162*>(&ev0.x));
        float2 e01 = __bfloat1622float2(*reinterpret_cast<__nv_bfloat162*>(&ev0.y));
        float2 h00 = __bfloat1622float2(*reinterpret_cast<__nv_bfloat162*>(&hv0.x));
        float2 h01 = __bfloat1622float2(*reinterpret_cast<__nv_bfloat162*>(&hv0.y));
        float2 e10 = __bfloat1622float2(*reinterpret_cast<__nv_bfloat162*>(&ev1.x));
        float2 e11 = __bfloat1622float2(*reinterpret_cast<__nv_bfloat162*>(&ev1.y));
        float2 h10 = __bfloat1622float2(*reinterpret_cast<__nv_bfloat162*>(&hv1.x));
        float2 h11 = __bfloat1622float2(*reinterpret_cast<__nv_bfloat162*>(&hv1.y));
        acc.x += fmaxf(e00.x + h00.x, 0.f) + fmaxf(e10.x + h10.x, 0.f);
        acc.y += fmaxf(e00.y + h00.y, 0.f) + fmaxf(e10.y + h10.y, 0.f);
        acc.z += fmaxf(e01.x + h01.x, 0.f) + fmaxf(e11.x + h11.x, 0.f);
        acc.w += fmaxf(e01.y + h01.y, 0.f) + fmaxf(e11.y + h11.y, 0.f);
    }
    if (j < jend) {
        int ei0 = eperm[j], si0 = sperm[j];
        uint2 ev0 = __ldcs(&e2[(size_t)ei0 * 32 + lane]);
        uint2 hv0 = hb2[(size_t)si0 * 32 + lane];
        float2 e00 = __bfloat1622float2(*reinterpret_cast<__nv_bfloat162*>(&ev0.x));
        float2 e01 = __bfloat1622float2(*reinterpret_cast<__nv_bfloat162*>(&ev0.y));
        float2 h00 = __bfloat1622float2(*reinterpret_cast<__nv_bfloat162*>(&hv0.x));
        float2 h01 = __bfloat1622float2(*reinterpret_cast<__nv_bfloat162*>(&hv0.y));
        acc.x += fmaxf(e00.x + h00.x, 0.f);
        acc.y += fmaxf(e00.y + h00.y, 0.f);
        acc.z += fmaxf(e01.x + h01.x, 0.f);
        acc.w += fmaxf(e01.y + h01.y, 0.f);
    }
    reinterpret_cast<float4*>(z)[w * 32 + lane] = acc;
}

// ---------------- pooling ----------------
__global__ void gate2_kernel(const float* __restrict__ hid, const float* __restrict__ w2,
                             const float* __restrict__ b2, float* __restrict__ gate, int n) {
    int w = (blockIdx.x * blockDim.x + threadIdx.x) >> 5;
    int lane = threadIdx.x & 31;
    if (w >= n) return;
    float s = hid[w * 64 + lane] * w2[lane] + hid[w * 64 + 32 + lane] * w2[32 + lane];
#pragma unroll
    for (int o = 16; o > 0; o >>= 1) s += __shfl_down_sync(0xffffffffu, s, o);
    if (lane == 0) gate[w] = s + b2[0];
}

__device__ __forceinline__ unsigned f2ord(float f) {
    unsigned b = __float_as_uint(f);
    return (b & 0x80000000u) ? ~b : (b | 0x80000000u);
}
__device__ __forceinline__ float ord2f(unsigned k) {
    return __uint_as_float((k & 0x80000000u) ? (k & 0x7fffffffu) : ~k);
}

__global__ void smax_kernel(const float* __restrict__ gate, const int* __restrict__ batch,
                            unsigned* __restrict__ gmaxk, int n) {
    int i = blockIdx.x * blockDim.x + threadIdx.x;
    if (i < n) atomicMax(&gmaxk[batch[i]], f2ord(gate[i]));
}

__global__ void wexp_kernel(const float* __restrict__ gate, const int* __restrict__ batch,
                            const unsigned* __restrict__ gmaxk, float* __restrict__ wexp,
                            float* __restrict__ den, int n) {
    int i = blockIdx.x * blockDim.x + threadIdx.x;
    if (i >= n) return;
    float m = ord2f(gmaxk[batch[i]]);
    float w = expf(gate[i] - m);
    wexp[i] = w;
    atomicAdd(&den[batch[i]], w);
}

__global__ void pool_kernel(const float* __restrict__ h, const int* __restrict__ batch,
                            const float* __restrict__ wexp, const float* __restrict__ den,
                            float* __restrict__ pool, int n) {
    int w = (blockIdx.x * blockDim.x + threadIdx.x) >> 5;
    int lane = threadIdx.x & 31;
    if (w >= n) return;
    int b = batch[w];
    float alpha = wexp[w] / den[b];
#pragma unroll
    for (int j = 0; j < 4; j++) {
        int c = lane + 32 * j;
        atomicAdd(&pool[b * HH + c], alpha * h[(size_t)w * HH + c]);
    }
}

__global__ void head2_kernel(const float* __restrict__ ht, const float* __restrict__ w2,
                             const float* __restrict__ b2, float* __restrict__ out,
                             int G, int T) {
    int i = blockIdx.x * blockDim.x + threadIdx.x;
    if (i >= G * T) return;
    int g = i / T, t = i - g * T;
    float s = b2[t];
    for (int k = 0; k < HH; k++) s += ht[g * HH + k] * w2[k * T + t];
    out[i] = s;
}

// ---------------- launch ----------------
extern "C" void kernel_launch(void* const* d_in, const int* in_sizes, int n_in,
                              void* d_out, int out_size) {
    const float* x = (const float*)d_in[0];
    const float* edge_attr = (const float*)d_in[1];
    const float* node_w = (const float*)d_in[2];
    const float* node_b = (const float*)d_in[3];
    const float* edge_w1 = (const float*)d_in[4];
    const float* edge_b1 = (const float*)d_in[5];
    const float* edge_w2 = (const float*)d_in[6];
    const float* edge_b2 = (const float*)d_in[7];
    const float* conv_w1 = (const float*)d_in[8];
    const float* conv_b1 = (const float*)d_in[9];
    const float* conv_w2 = (const float*)d_in[10];
    const float* conv_b2 = (const float*)d_in[11];
    const float* bn_gamma = (const float*)d_in[12];
    const float* bn_beta = (const float*)d_in[13];
    const float* gate_w1 = (const float*)d_in[14];
    const float* gate_b1 = (const float*)d_in[15];
    const float* gate_w2 = (const float*)d_in[16];
    const float* gate_b2 = (const float*)d_in[17];
    const float* head_w1 = (const float*)d_in[18];
    const float* head_b1 = (const float*)d_in[19];
    const float* head_w2 = (const float*)d_in[20];
    const float* head_b2 = (const float*)d_in[21];
    const int* edge_index = (const int*)d_in[22];
    const int* batch = (const int*)d_in[23];

    const int N = in_sizes[0] / 64;
    const int E = in_sizes[22] / 2;
    const int T = 5;
    const int G = out_size / T;

    float *h, *z, *tb, *gate, *wexp, *den, *pool, *ht;
    __nv_bfloat16 *e, *hb;
    int *deg, *off, *cur, *bsum, *eperm, *sperm;
    unsigned* gmaxk;
    cudaGetSymbolAddress((void**)&h, g_h);
    cudaGetSymbolAddress((void**)&hb, g_hb);
    cudaGetSymbolAddress((void**)&z, g_z);
    cudaGetSymbolAddress((void**)&tb, g_tb);
    cudaGetSymbolAddress((void**)&e, g_e);
    cudaGetSymbolAddress((void**)&deg, g_deg);
    cudaGetSymbolAddress((void**)&off, g_off);
    cudaGetSymbolAddress((void**)&cur, g_cur);
    cudaGetSymbolAddress((void**)&bsum, g_bsum);
    cudaGetSymbolAddress((void**)&eperm, g_eperm);
    cudaGetSymbolAddress((void**)&sperm, g_sperm);
    cudaGetSymbolAddress((void**)&gate, g_gate);
    cudaGetSymbolAddress((void**)&wexp, g_wexp);
    cudaGetSymbolAddress((void**)&gmaxk, g_gmaxk);
    cudaGetSymbolAddress((void**)&den, g_den);
    cudaGetSymbolAddress((void**)&pool, g_pool);
    cudaGetSymbolAddress((void**)&ht, g_ht);

    __nv_bfloat16 *wnh, *wnl, *c1h, *c1l, *c2h, *c2l, *wgh, *wgl, *whh, *whl,
        *e1h, *e1l, *e2h, *e2l;
    cudaGetSymbolAddress((void**)&wnh, g_wnh); cudaGetSymbolAddress((void**)&wnl, g_wnl);
    cudaGetSymbolAddress((void**)&c1h, g_c1h); cudaGetSymbolAddress((void**)&c1l, g_c1l);
    cudaGetSymbolAddress((void**)&c2h, g_c2h); cudaGetSymbolAddress((void**)&c2l, g_c2l);
    cudaGetSymbolAddress((void**)&wgh, g_wgh); cudaGetSymbolAddress((void**)&wgl, g_wgl);
    cudaGetSymbolAddress((void**)&whh, g_whh); cudaGetSymbolAddress((void**)&whl, g_whl);
    cudaGetSymbolAddress((void**)&e1h, g_e1h); cudaGetSymbolAddress((void**)&e1l, g_e1l);
    cudaGetSymbolAddress((void**)&e2h, g_e2h); cudaGetSymbolAddress((void**)&e2l, g_e2l);

    // dynamic smem sizes (bytes)
    const int SM_N1 = (2 * 128 * 72 + 2 * 64 * 136) * 2;
    const int SM_G = (2 * 128 * 136 + 2 * 128 * 72) * 2;
    const int SM_H = (2 * 128 * 136 + 2 * 128 * 136) * 2;
    const int SM_CONV = 6 * 128 * 136 * 2;
    const int SM_EDGE = (128 * 24 + 16 * 136 + 128 * 136 + 128 * 136) * 2;  // 80128
    cudaFuncSetAttribute(mma_gemm<64, 128, false, true>, cudaFuncAttributeMaxDynamicSharedMemorySize, SM_N1);
    cudaFuncSetAttribute(mma_gemm<128, 64, true, false>, cudaFuncAttributeMaxDynamicSharedMemorySize, SM_G);
    cudaFuncSetAttribute(mma_gemm<128, 128, true, false>, cudaFuncAttributeMaxDynamicSharedMemorySize, SM_H);
    cudaFuncSetAttribute(conv_fused_kernel, cudaFuncAttributeMaxDynamicSharedMemorySize, SM_CONV);
    cudaFuncSetAttribute(edge_mma_kernel, cudaFuncAttributeMaxDynamicSharedMemorySize, SM_EDGE);

    // zero scratch
    cudaMemsetAsync(deg, 0, (size_t)N * 4, 0);
    cudaMemsetAsync(cur, 0, (size_t)N * 4, 0);
    cudaMemsetAsync(gmaxk, 0, (size_t)G * 4, 0);
    cudaMemsetAsync(den, 0, (size_t)G * 4, 0);
    cudaMemsetAsync(pool, 0, (size_t)G * HH * 4, 0);

    // weight prep (split + pad)
    wconv_kernel<<<(64 * 136 + 255) / 256, 256>>>(node_w, 64, 128, 136, wnh, wnl);
    for (int l = 0; l < 4; l++) {
        wconv_kernel<<<(128 * 136 + 255) / 256, 256>>>(
            conv_w1 + (size_t)l * 16384, 128, 128, 136,
            c1h + (size_t)l * 128 * 136, c1l + (size_t)l * 128 * 136);
        wconv_kernel<<<(128 * 136 + 255) / 256, 256>>>(
            conv_w2 + (size_t)l * 16384, 128, 128, 136,
            c2h + (size_t)l * 128 * 136, c2l + (size_t)l * 128 * 136);
    }
    wconv_kernel<<<(128 * 72 + 255) / 256, 256>>>(gate_w1, 128, 64, 72, wgh, wgl);
    wconv_kernel<<<(128 * 136 + 255) / 256, 256>>>(head_w1, 128, 128, 136, whh, whl);
    wconv_kernel<<<(16 * 136 + 255) / 256, 256>>>(edge_w1, 16, 128, 136, e1h, e1l);
    wconv_kernel<<<(128 * 136 + 255) / 256, 256>>>(edge_w2, 128, 128, 136, e2h, e2l);

    // CSR by dst (multi-block scan)
    const int NB = (N + 1023) / 1024;
    hist_kernel<<<(E + 255) / 256, 256>>>(edge_index, deg, E);
    scan1_kernel<<<NB, 1024>>>(deg, off, bsum, N);
    scan2_kernel<<<1, 32>>>(bsum, NB);
    scan3_kernel<<<(N + 255) / 256, 256>>>(off, bsum, N);
    scatter_kernel<<<(E + 255) / 256, 256>>>(edge_index, off, cur, eperm, sperm, E);

    // encoders
    mma_gemm<64, 128, false, true><<<(N + 127) / 128, 256, SM_N1>>>(
        x, wnh, wnl, node_b, h, hb, N);
    edge_mma_kernel<<<(E + 127) / 128, 256, SM_EDGE>>>(
        edge_attr, e1h, e2h, edge_b1, edge_b2, e, E);

    // 4 GINE layers
    for (int l = 0; l < 4; l++) {
        aggregate_kernel<<<(N + 7) / 8, 256>>>(h, hb, e, off, deg, eperm, sperm, z, N);
        conv_fused_kernel<<<(N + 127) / 128, 256, SM_CONV>>>(
            z, c1h + (size_t)l * 128 * 136, c1l + (size_t)l * 128 * 136,
            c2h + (size_t)l * 128 * 136, c2l + (size_t)l * 128 * 136,
            conv_b1 + l * HH, conv_b2 + l * HH,
            bn_gamma + l * HH, bn_beta + l * HH, h, hb, N);
    }

    // gate MLP + segment softmax pooling
    mma_gemm<128, 64, true, false><<<(N + 127) / 128, 256, SM_G>>>(
        h, wgh, wgl, gate_b1, tb, nullptr, N);
    gate2_kernel<<<(N + 7) / 8, 256>>>(tb, gate_w2, gate_b2, gate, N);
    smax_kernel<<<(N + 255) / 256, 256>>>(gate, batch, gmaxk, N);
    wexp_kernel<<<(N + 255) / 256, 256>>>(gate, batch, gmaxk, wexp, den, N);
    pool_kernel<<<(N + 7) / 8, 256>>>(h, batch, wexp, den, pool, N);

    // head
    mma_gemm<128, 128, true, false><<<(G + 127) / 128, 256, SM_H>>>(
        pool, whh, whl, head_b1, ht, nullptr, G);
    head2_kernel<<<(G * T + 255) / 256, 256>>>(ht, head_w2, head_b2, (float*)d_out, G, T);
}